// round 7
// baseline (speedup 1.0000x reference)
#include <cuda_runtime.h>
#include <cuda_bf16.h>
#include <stdint.h>
#include <math.h>

#define BATCH 256
#define NU    300
#define LIN   608
#define FLT   19
#define POOL  7
#define LP    84
#define HID   100
#define NCLS  50
#define EPSV  1e-5f

#define MTILES 19            // 304 unit rows
#define KSTEPS 5             // 5 x k16 = 80 >= 76
#define WARPS  14
#define CTHREADS (WARPS * 32)  // 448
#define NCH    14            // pools per chunk
#define NCHUNKS 6            // 6 * 14 = 84
#define BPC    2             // batches per CTA (grid 128)

typedef unsigned long long u64;

// scratch (device globals)
__device__ float g_y[NU * LP * BATCH];   // [u][f][b]
__device__ float g_z[NU * BATCH];        // [u][b]

// ---------------------------------------------------------------------------
// smem byte offsets (dynamic smem)
// ---------------------------------------------------------------------------
#define ASZ    (MTILES * KSTEPS * 512)        // 48640 per split
#define BBUF   (NCH * KSTEPS * 256)           // 17920 per split per buffer
#define SA_HI  0
#define SA_LO  (SA_HI + ASZ)                  // 48640
#define SB0_HI (SA_LO + ASZ)                  // 97280
#define SB0_LO (SB0_HI + BBUF)
#define SB1_HI (SB0_LO + BBUF)
#define SB1_LO (SB1_HI + BBUF)
#define SXH    (SB1_LO + BBUF)                // 168960
#define SXL    (SXH + 4864)
#define SBN_S  (SXL + 4864)
#define SBN_C  (SBN_S + 1200)
#define SMTOT  (SBN_C + 1200)                 // 181088

__device__ __forceinline__ uint32_t smem_u32(const void* p) {
    uint32_t a;
    asm("{ .reg .u64 t; cvta.to.shared.u64 t, %1; cvt.u32.u64 %0, t; }"
        : "=r"(a) : "l"(p));
    return a;
}

#define LDSM4(r, a) \
    asm volatile("ldmatrix.sync.aligned.m8n8.x4.shared.b16 {%0,%1,%2,%3}, [%4];" \
        : "=r"((r)[0]), "=r"((r)[1]), "=r"((r)[2]), "=r"((r)[3]) : "r"(a))
#define LDSM2(r, a) \
    asm volatile("ldmatrix.sync.aligned.m8n8.x2.shared.b16 {%0,%1}, [%2];" \
        : "=r"((r)[0]), "=r"((r)[1]) : "r"(a))

__device__ __forceinline__ void mma16816(float* c, const uint32_t* a, const uint32_t* b) {
    asm volatile(
        "mma.sync.aligned.m16n8k16.row.col.f32.bf16.bf16.f32 "
        "{%0,%1,%2,%3}, {%4,%5,%6,%7}, {%8,%9}, {%0,%1,%2,%3};"
        : "+f"(c[0]), "+f"(c[1]), "+f"(c[2]), "+f"(c[3])
        : "r"(a[0]), "r"(a[1]), "r"(a[2]), "r"(a[3]), "r"(b[0]), "r"(b[1]));
}

// epilogue for one m-tile's accumulators (2 subchains x 4 regs)
#define EPI(ACC, MT) do {                                                      \
    const float f0 = (ACC)[0][0] + (ACC)[1][0];                                \
    const float f1 = (ACC)[0][1] + (ACC)[1][1];                                \
    const float f2 = (ACC)[0][2] + (ACC)[1][2];                                \
    const float f3 = (ACC)[0][3] + (ACC)[1][3];                                \
    float mA = fmaxf(f0, f1), mB = fmaxf(f2, f3);                              \
    mA = fmaxf(mA, __shfl_xor_sync(0xFFFFFFFFu, mA, 1));                       \
    mA = fmaxf(mA, __shfl_xor_sync(0xFFFFFFFFu, mA, 2));                       \
    mB = fmaxf(mB, __shfl_xor_sync(0xFFFFFFFFu, mB, 1));                       \
    mB = fmaxf(mB, __shfl_xor_sync(0xFFFFFFFFu, mB, 2));                       \
    if ((lane & 3) == 0) {                                                     \
        const int g  = lane >> 2;                                              \
        const int u0 = (MT) * 16 + g;                                          \
        const int u1 = u0 + 8;                                                 \
        g_y[((size_t)u0 * LP + fpool) * BATCH + b] =                           \
            __expf(fmaf(mA, s1s[u0], c1s[u0]));                                \
        if (u1 < NU)                                                           \
            g_y[((size_t)u1 * LP + fpool) * BATCH + b] =                       \
                __expf(fmaf(mB, s1s[u1], c1s[u1]));                            \
    }                                                                          \
} while (0)

// ---------------------------------------------------------------------------
// Kernel A: conv as warp-HMMA GEMM (split-bf16 3-pass) + fused BN/exp/maxpool
// 14 warps, 1 pool/warp/chunk, acc ping-pong (deferred epilogue),
// double-buffered B chunks (1 barrier per chunk).
// ---------------------------------------------------------------------------
__global__ __launch_bounds__(CTHREADS, 1) void conv_mma_kernel(
    const float* __restrict__ x,  const float* __restrict__ w1,
    const float* __restrict__ b1, const float* __restrict__ g1,
    const float* __restrict__ be1,const float* __restrict__ m1,
    const float* __restrict__ v1)
{
    extern __shared__ __align__(128) char smem[];
    const uint32_t sb = smem_u32(smem);

    const int tid  = threadIdx.x;
    const int wid  = tid >> 5;
    const int lane = tid & 31;

    __nv_bfloat16* xh = reinterpret_cast<__nv_bfloat16*>(smem + SXH);
    __nv_bfloat16* xl = reinterpret_cast<__nv_bfloat16*>(smem + SXL);
    float* s1s = reinterpret_cast<float*>(smem + SBN_S);
    float* c1s = reinterpret_cast<float*>(smem + SBN_C);

    // --- BN constants (once) ---
    for (int i = tid; i < NU; i += CTHREADS) {
        const float s = g1[i] * rsqrtf(v1[i] + EPSV);
        s1s[i] = s;
        c1s[i] = (b1[i] - m1[i]) * s + be1[i];
    }
    // --- A build (once): W (304x80, zero-padded), ldmatrix-mat layout, hi/lo ---
    {
        __nv_bfloat16* aH = reinterpret_cast<__nv_bfloat16*>(smem + SA_HI);
        __nv_bfloat16* aL = reinterpret_cast<__nv_bfloat16*>(smem + SA_LO);
        for (int i = tid; i < 304 * 80; i += CTHREADS) {
            const int ul = i / 80;
            const int k  = i % 80;
            float v = 0.f;
            if (ul < NU && k < 76) v = w1[ul * 76 + k];
            const __nv_bfloat16 h = __float2bfloat16(v);
            const __nv_bfloat16 l = __float2bfloat16(v - __bfloat162float(h));
            const int mt  = ul >> 4, s = k >> 4;
            const int mat = ((ul & 15) >> 3) | (((k & 15) >> 3) << 1);
            const int off = ((((mt * KSTEPS + s) << 2) + mat) << 6)
                            + ((ul & 7) << 3) + (k & 7);   // bf16 units
            aH[off] = h;
            aL[off] = l;
        }
    }

    const uint32_t aBaseH = sb + SA_HI + lane * 16;
    const uint32_t aBaseL = sb + SA_LO + lane * 16;
    const int L2 = lane & 15;
    const uint32_t bOff = ((L2 >> 3) << 7) + ((L2 & 7) << 4);

    for (int bi = 0; bi < BPC; bi++) {
        const int b = blockIdx.x * BPC + bi;

        // --- x load + hi/lo split ---
        {
            const float* xg = x + (size_t)b * (4 * LIN);
            for (int i = tid; i < 4 * LIN; i += CTHREADS) {
                const float v = xg[i];
                const __nv_bfloat16 h = __float2bfloat16(v);
                xh[i] = h;
                xl[i] = __float2bfloat16(v - __bfloat162float(h));
            }
        }
        __syncthreads();   // xh/xl (and, bi==0, A/BN) visible

        // --- build chunk 0 into buffer 0 ---
#define BUILD_B(NT, BHI, BLO) do {                                             \
        for (int i = tid; i < NCH * 8 * 80; i += CTHREADS) {                   \
            const int p  = i / 640;                                            \
            const int r  = i % 640;                                            \
            const int j  = r / 80;                                             \
            const int k  = r % 80;                                             \
            const int jj = (j == 7) ? 0 : j;                                   \
            __nv_bfloat16 vh = __float2bfloat16(0.f);                          \
            __nv_bfloat16 vl = vh;                                             \
            if (k < 76) {                                                      \
                const int c  = k / FLT, kk = k % FLT;                          \
                const int xi = c * LIN + 7 * ((NT) * NCH + p) + jj + kk;       \
                vh = xh[xi];                                                   \
                vl = xl[xi];                                                   \
            }                                                                  \
            const int off = (((p * KSTEPS + (k >> 4)) << 1) + ((k & 15) >> 3)) * 128 \
                            + (j << 4) + ((k & 7) << 1);                       \
            *reinterpret_cast<__nv_bfloat16*>(smem + (BHI) + off) = vh;        \
            *reinterpret_cast<__nv_bfloat16*>(smem + (BLO) + off) = vl;        \
        }                                                                      \
    } while (0)

        BUILD_B(0, SB0_HI, SB0_LO);

        for (int nt = 0; nt < NCHUNKS; nt++) {
            __syncthreads();   // B[nt] visible; all prior LDSMs retired

            const uint32_t bHI = (nt & 1) ? SB1_HI : SB0_HI;
            const uint32_t bLO = (nt & 1) ? SB1_LO : SB0_LO;

            // --- B fragments -> registers (this warp's pool = wid) ---
            uint32_t bh[KSTEPS][2], bl[KSTEPS][2];
#pragma unroll
            for (int s = 0; s < KSTEPS; s++) {
                const uint32_t tb = (wid * KSTEPS + s) * 256 + bOff;
                LDSM2(bh[s], sb + bHI + tb);
                LDSM2(bl[s], sb + bLO + tb);
            }

            // --- build next chunk while MMAs run (no barrier until next nt) ---
            if (nt + 1 < NCHUNKS) {
                if (nt & 1) BUILD_B(nt + 1, SB0_HI, SB0_LO);
                else        BUILD_B(nt + 1, SB1_HI, SB1_LO);
            }

            const int fpool = nt * NCH + wid;

            // --- m-tile stream with acc ping-pong (deferred epilogue) ---
            float acc[2][2][4];
            uint32_t ah[KSTEPS][4], al[KSTEPS][4];

#pragma unroll 1
            for (int mt = 0; mt < MTILES; mt++) {
                const int cur = mt & 1;
#pragma unroll
                for (int s = 0; s < KSTEPS; s++) {
                    LDSM4(ah[s], aBaseH + (mt * KSTEPS + s) * 512);
                    LDSM4(al[s], aBaseL + (mt * KSTEPS + s) * 512);
                }
#pragma unroll
                for (int s2 = 0; s2 < 2; s2++)
#pragma unroll
                    for (int q = 0; q < 4; q++) acc[cur][s2][q] = 0.f;

#pragma unroll
                for (int t = 0; t < 15; t++) {
                    const int s = t / 3, pz = t % 3;
                    mma16816(acc[cur][t & 1],
                             pz == 2 ? al[s] : ah[s],
                             pz == 1 ? bl[s] : bh[s]);
                }
                if (mt > 0)
                    EPI(acc[cur ^ 1], mt - 1);
            }
            EPI(acc[(MTILES - 1) & 1], MTILES - 1);
        }
    }
}

// ---------------------------------------------------------------------------
// packed f32x2 helpers (MLP kernel)
// ---------------------------------------------------------------------------
__device__ __forceinline__ u64 pack2(float a, float b) {
    u64 r;
    asm("mov.b64 %0, {%1, %2};" : "=l"(r) : "f"(a), "f"(b));
    return r;
}
__device__ __forceinline__ void fma2(u64 &d, u64 a, u64 b) {
    asm("fma.rn.f32x2 %0, %1, %2, %0;" : "+l"(d) : "l"(a), "l"(b));
}
__device__ __forceinline__ void unpack2(float &lo, float &hi, u64 v) {
    unsigned a, b;
    asm("mov.b64 {%0, %1}, %2;" : "=r"(a), "=r"(b) : "l"(v));
    lo = __uint_as_float(a); hi = __uint_as_float(b);
}

// ---------------------------------------------------------------------------
// Kernel B: per-unit MLP 84->100 (BN+ReLU) -> 100->1 (BN+ReLU)  ->  z[u][b]
// ---------------------------------------------------------------------------
__global__ __launch_bounds__(BATCH) void unit_mlp_kernel(
    const float* __restrict__ w2, const float* __restrict__ b2,
    const float* __restrict__ g2, const float* __restrict__ be2,
    const float* __restrict__ m2, const float* __restrict__ v2,
    const float* __restrict__ w3, const float* __restrict__ b3,
    const float* __restrict__ g3, const float* __restrict__ be3,
    const float* __restrict__ m3, const float* __restrict__ v3)
{
    __shared__ __align__(16) float w2s[HID * LP];
    __shared__ float s2s[HID], c2s[HID], w3s[HID];

    const int u   = blockIdx.x;
    const int tid = threadIdx.x;

    for (int i = tid; i < HID * LP; i += BATCH)
        w2s[i] = w2[u * HID * LP + i];
    if (tid < HID) {
        const int idx = u * HID + tid;
        float s = g2[idx] * rsqrtf(v2[idx] + EPSV);
        s2s[tid] = s;
        c2s[tid] = (b2[idx] - m2[idx]) * s + be2[idx];
        w3s[tid] = w3[idx];
    }
    __syncthreads();

    u64 yv2[LP / 2];
#pragma unroll
    for (int fp = 0; fp < LP / 2; fp++) {
        const float a  = g_y[u * (LP * BATCH) + (2 * fp) * BATCH + tid];
        const float bb = g_y[u * (LP * BATCH) + (2 * fp + 1) * BATCH + tid];
        yv2[fp] = pack2(a, bb);
    }

    float zacc = 0.0f;
#pragma unroll 1
    for (int o = 0; o < HID; o++) {
        const float4* wrow = reinterpret_cast<const float4*>(&w2s[o * LP]);
        u64 a0 = 0ULL, a1 = 0ULL;
#pragma unroll
        for (int j = 0; j < LP / 4; j++) {
            float4 v = wrow[j];
            u64 w01 = pack2(v.x, v.y);
            u64 w23 = pack2(v.z, v.w);
            fma2(a0, yv2[2 * j], w01);
            fma2(a1, yv2[2 * j + 1], w23);
        }
        float l0, h0, l1, h1;
        unpack2(l0, h0, a0);
        unpack2(l1, h1, a1);
        const float dsum = (l0 + h0) + (l1 + h1);
        const float hv = fmaxf(fmaf(dsum, s2s[o], c2s[o]), 0.0f);
        zacc = fmaf(hv, w3s[o], zacc);
    }

    const float s3 = g3[u] * rsqrtf(v3[u] + EPSV);
    const float z  = fmaf(zacc + b3[u] - m3[u], s3, be3[u]);
    g_z[u * BATCH + tid] = fmaxf(z, 0.0f);
}

// ---------------------------------------------------------------------------
// Kernel C: out[b][c] = sum_u z[u][b] * wf[c][u] + bf[c]
// ---------------------------------------------------------------------------
__global__ __launch_bounds__(BATCH) void final_linear_kernel(
    const float* __restrict__ wf, const float* __restrict__ bf,
    float* __restrict__ out)
{
    __shared__ float wfs[NU];
    const int c   = blockIdx.x;
    const int tid = threadIdx.x;

    for (int i = tid; i < NU; i += BATCH)
        wfs[i] = wf[c * NU + i];
    __syncthreads();

    float acc = bf[c];
#pragma unroll 4
    for (int u = 0; u < NU; u++)
        acc = fmaf(g_z[u * BATCH + tid], wfs[u], acc);

    out[tid * NCLS + c] = acc;
}

// ---------------------------------------------------------------------------
extern "C" void kernel_launch(void* const* d_in, const int* in_sizes, int n_in,
                              void* d_out, int out_size)
{
    const float* x   = (const float*)d_in[0];
    const float* w1  = (const float*)d_in[1];
    const float* b1  = (const float*)d_in[2];
    const float* g1  = (const float*)d_in[3];
    const float* be1 = (const float*)d_in[4];
    const float* m1  = (const float*)d_in[5];
    const float* v1  = (const float*)d_in[6];
    const float* w2  = (const float*)d_in[7];
    const float* b2  = (const float*)d_in[8];
    const float* g2  = (const float*)d_in[9];
    const float* be2 = (const float*)d_in[10];
    const float* m2  = (const float*)d_in[11];
    const float* v2  = (const float*)d_in[12];
    const float* w3  = (const float*)d_in[13];
    const float* b3  = (const float*)d_in[14];
    const float* g3  = (const float*)d_in[15];
    const float* be3 = (const float*)d_in[16];
    const float* m3  = (const float*)d_in[17];
    const float* v3  = (const float*)d_in[18];
    const float* wf  = (const float*)d_in[19];
    const float* bf  = (const float*)d_in[20];
    float* out = (float*)d_out;

    cudaFuncSetAttribute(conv_mma_kernel,
                         cudaFuncAttributeMaxDynamicSharedMemorySize, SMTOT);

    conv_mma_kernel<<<BATCH / BPC, CTHREADS, SMTOT>>>(x, w1, b1, g1, be1, m1, v1);
    unit_mlp_kernel<<<NU, BATCH>>>(w2, b2, g2, be2, m2, v2,
                                   w3, b3, g3, be3, m3, v3);
    final_linear_kernel<<<NCLS, BATCH>>>(wf, bf, out);
}

// round 8
// speedup vs baseline: 1.3562x; 1.3562x over previous
#include <cuda_runtime.h>
#include <cuda_fp16.h>
#include <stdint.h>
#include <math.h>

#define BATCH 256
#define NU    300
#define LIN   608
#define FLT   19
#define POOL  7
#define LP    84
#define HID   100
#define NCLS  50
#define EPSV  1e-5f

#define MTILES 19            // 304 unit rows
#define KSTEPS 5             // 5 x k16 = 80 >= 76
#define WARPS  14
#define CTHREADS (WARPS * 32)  // 448
#define NCH    28            // pools per chunk (2 per warp)
#define NCHUNKS 3            // 3 * 28 = 84
#define BPC    2             // batches per CTA (grid 128)

typedef unsigned long long u64;

// scratch (device globals)
__device__ float g_y[NU * LP * BATCH];   // [u][f][b]
__device__ float g_z[NU * BATCH];        // [u][b]

// ---------------------------------------------------------------------------
// smem byte offsets (dynamic smem)
// ---------------------------------------------------------------------------
#define ASZ    (MTILES * KSTEPS * 512)        // 48640 (fp16 single)
#define BBUF   (NCH * KSTEPS * 256)           // 35840 per buffer
#define SA     0
#define SB0    (SA + ASZ)                     // 48640
#define SB1    (SB0 + BBUF)                   // 84480
#define SXH    (SB1 + BBUF)                   // 120320 (2432 fp16)
#define SBN_S  (SXH + 4864)                   // 125184
#define SBN_C  (SBN_S + 1200)                 // 126384
#define SMTOT  (SBN_C + 1200)                 // 127584

__device__ __forceinline__ uint32_t smem_u32(const void* p) {
    uint32_t a;
    asm("{ .reg .u64 t; cvta.to.shared.u64 t, %1; cvt.u32.u64 %0, t; }"
        : "=r"(a) : "l"(p));
    return a;
}

#define LDSM4(r, a) \
    asm volatile("ldmatrix.sync.aligned.m8n8.x4.shared.b16 {%0,%1,%2,%3}, [%4];" \
        : "=r"((r)[0]), "=r"((r)[1]), "=r"((r)[2]), "=r"((r)[3]) : "r"(a))
#define LDSM2(r, a) \
    asm volatile("ldmatrix.sync.aligned.m8n8.x2.shared.b16 {%0,%1}, [%2];" \
        : "=r"((r)[0]), "=r"((r)[1]) : "r"(a))

__device__ __forceinline__ void mma16816(float* c, const uint32_t* a, const uint32_t* b) {
    asm volatile(
        "mma.sync.aligned.m16n8k16.row.col.f32.f16.f16.f32 "
        "{%0,%1,%2,%3}, {%4,%5,%6,%7}, {%8,%9}, {%0,%1,%2,%3};"
        : "+f"(c[0]), "+f"(c[1]), "+f"(c[2]), "+f"(c[3])
        : "r"(a[0]), "r"(a[1]), "r"(a[2]), "r"(a[3]), "r"(b[0]), "r"(b[1]));
}

// epilogue for one m-tile, 2 pools: packed butterfly max + single store path
#define EPI2(ACCP, MT) do {                                                    \
    _Pragma("unroll") for (int r = 0; r < 2; r++) {                            \
        float mA = fmaxf((ACCP)[r][0], (ACCP)[r][1]);                          \
        float mB = fmaxf((ACCP)[r][2], (ACCP)[r][3]);                          \
        mA = fmaxf(mA, __shfl_xor_sync(0xFFFFFFFFu, mA, 1));                   \
        mB = fmaxf(mB, __shfl_xor_sync(0xFFFFFFFFu, mB, 1));                   \
        float cb = (lane & 1) ? mB : mA;                                       \
        cb = fmaxf(cb, __shfl_xor_sync(0xFFFFFFFFu, cb, 2));                   \
        if ((lane & 2) == 0) {                                                 \
            const int u = (MT) * 16 + (lane >> 2) + ((lane & 1) << 3);         \
            if (u < NU)                                                        \
                g_y[((size_t)u * LP + (fpool0 + r)) * BATCH + b] =             \
                    __expf(fmaf(cb, s1s[u], c1s[u]));                          \
        }                                                                      \
    }                                                                          \
} while (0)

// ---------------------------------------------------------------------------
// Kernel A: conv as warp-HMMA GEMM (fp16 single-pass) + fused BN/exp/maxpool
// 14 warps, 2 pools/warp/chunk, 3 chunks, acc ping-pong, double-buffered B.
// ---------------------------------------------------------------------------
__global__ __launch_bounds__(CTHREADS, 1) void conv_mma_kernel(
    const float* __restrict__ x,  const float* __restrict__ w1,
    const float* __restrict__ b1, const float* __restrict__ g1,
    const float* __restrict__ be1,const float* __restrict__ m1,
    const float* __restrict__ v1)
{
    extern __shared__ __align__(128) char smem[];
    const uint32_t sb = smem_u32(smem);

    const int tid  = threadIdx.x;
    const int wid  = tid >> 5;
    const int lane = tid & 31;

    __half* xh = reinterpret_cast<__half*>(smem + SXH);
    float* s1s = reinterpret_cast<float*>(smem + SBN_S);
    float* c1s = reinterpret_cast<float*>(smem + SBN_C);

    // --- BN constants (once) ---
    for (int i = tid; i < NU; i += CTHREADS) {
        const float s = g1[i] * rsqrtf(v1[i] + EPSV);
        s1s[i] = s;
        c1s[i] = (b1[i] - m1[i]) * s + be1[i];
    }
    // --- A build (once): W (304x80, zero-padded), ldmatrix-mat layout, fp16 ---
    {
        __half* aS = reinterpret_cast<__half*>(smem + SA);
        for (int i = tid; i < 304 * 80; i += CTHREADS) {
            const int ul = i / 80;
            const int k  = i % 80;
            float v = 0.f;
            if (ul < NU && k < 76) v = w1[ul * 76 + k];
            const int mt  = ul >> 4, s = k >> 4;
            const int mat = ((ul & 15) >> 3) | (((k & 15) >> 3) << 1);
            const int off = ((((mt * KSTEPS + s) << 2) + mat) << 6)
                            + ((ul & 7) << 3) + (k & 7);   // fp16 units
            aS[off] = __float2half_rn(v);
        }
    }

    const uint32_t aBase  = sb + SA + lane * 16;
    const uint32_t a4off  = ((lane >> 3) << 7) + ((lane & 7) << 4);
    const uint32_t a2off  = (((lane & 15) >> 3) << 7) + ((lane & 7) << 4);

    // build B chunk: pool-major im2col, fp16, half2-paired stores
#define BUILD_B(NT, BOFS) do {                                                 \
        for (int i = tid; i < NCH * 8 * 40; i += CTHREADS) {                   \
            const int p  = i / 320;                                            \
            const int r  = i % 320;                                            \
            const int j  = r / 40;                                             \
            const int k  = (r % 40) * 2;                                       \
            const int jj = (j == 7) ? 0 : j;                                   \
            __half v0 = __float2half_rn(0.f), v1h = v0;                        \
            if (k < 76) {                                                      \
                const int base7 = 7 * ((NT) * NCH + p) + jj;                   \
                const int c0 = k / FLT, k1 = k + 1, c1 = k1 / FLT;             \
                v0  = xh[c0 * LIN + base7 + (k - c0 * FLT)];                   \
                v1h = xh[c1 * LIN + base7 + (k1 - c1 * FLT)];                  \
            }                                                                  \
            const int off = (((p * KSTEPS + (k >> 4)) << 1) + ((k & 15) >> 3)) * 128 \
                            + (j << 4) + ((k & 7) << 1);                       \
            *reinterpret_cast<__half2*>(smem + (BOFS) + off) =                 \
                __halves2half2(v0, v1h);                                       \
        }                                                                      \
    } while (0)

    for (int bi = 0; bi < BPC; bi++) {
        const int b = blockIdx.x * BPC + bi;

        // --- x load + fp16 round ---
        {
            const float* xg = x + (size_t)b * (4 * LIN);
            for (int i = tid; i < 4 * LIN; i += CTHREADS)
                xh[i] = __float2half_rn(xg[i]);
        }
        __syncthreads();   // xh visible (and A/BN on bi==0); prior-batch LDSMs retired

        BUILD_B(0, SB0);

        for (int nt = 0; nt < NCHUNKS; nt++) {
            __syncthreads();   // B[nt] visible

            const uint32_t bbase = sb + ((nt & 1) ? SB1 : SB0)
                                   + (uint32_t)(2 * wid) * (KSTEPS * 256);

            // --- B fragments -> registers: 2 pools x 5 ksteps ---
            uint32_t bfr[2][KSTEPS][2];
#pragma unroll
            for (int p = 0; p < 2; p++) {
                const uint32_t pb = bbase + p * (KSTEPS * 256);
                LDSM4(&bfr[p][0][0], pb + a4off);            // s0,s1
                LDSM4(&bfr[p][2][0], pb + 512 + a4off);      // s2,s3
                LDSM2(&bfr[p][4][0], pb + 1024 + a2off);     // s4
            }

            // --- build next chunk while MMAs run ---
            if (nt + 1 < NCHUNKS) {
                if (nt & 1) BUILD_B(nt + 1, SB0);
                else        BUILD_B(nt + 1, SB1);
            }

            const int fpool0 = nt * NCH + 2 * wid;

            // --- m-tile stream, acc ping-pong (deferred epilogue) ---
            float acc[2][2][4];
            uint32_t ah[KSTEPS][4];

#pragma unroll 1
            for (int mt = 0; mt < MTILES; mt++) {
                const int cur = mt & 1;
#pragma unroll
                for (int s = 0; s < KSTEPS; s++)
                    LDSM4(ah[s], aBase + (mt * KSTEPS + s) * 512);
#pragma unroll
                for (int p = 0; p < 2; p++)
#pragma unroll
                    for (int q = 0; q < 4; q++) acc[cur][p][q] = 0.f;

                if (mt > 0)
                    EPI2(acc[cur ^ 1], mt - 1);

#pragma unroll
                for (int s = 0; s < KSTEPS; s++) {
                    mma16816(acc[cur][0], ah[s], bfr[0][s]);
                    mma16816(acc[cur][1], ah[s], bfr[1][s]);
                }
            }
            EPI2(acc[(MTILES - 1) & 1], MTILES - 1);
        }
        __syncthreads();   // all LDSMs of last chunk done before xh overwrite
    }
}

// ---------------------------------------------------------------------------
// packed f32x2 helpers (MLP kernel)
// ---------------------------------------------------------------------------
__device__ __forceinline__ u64 pack2(float a, float b) {
    u64 r;
    asm("mov.b64 %0, {%1, %2};" : "=l"(r) : "f"(a), "f"(b));
    return r;
}
__device__ __forceinline__ void fma2(u64 &d, u64 a, u64 b) {
    asm("fma.rn.f32x2 %0, %1, %2, %0;" : "+l"(d) : "l"(a), "l"(b));
}
__device__ __forceinline__ void unpack2(float &lo, float &hi, u64 v) {
    unsigned a, b;
    asm("mov.b64 {%0, %1}, %2;" : "=r"(a), "=r"(b) : "l"(v));
    lo = __uint_as_float(a); hi = __uint_as_float(b);
}

// ---------------------------------------------------------------------------
// Kernel B: per-unit MLP 84->100 (BN+ReLU) -> 100->1 (BN+ReLU)  ->  z[u][b]
// ---------------------------------------------------------------------------
__global__ __launch_bounds__(BATCH) void unit_mlp_kernel(
    const float* __restrict__ w2, const float* __restrict__ b2,
    const float* __restrict__ g2, const float* __restrict__ be2,
    const float* __restrict__ m2, const float* __restrict__ v2,
    const float* __restrict__ w3, const float* __restrict__ b3,
    const float* __restrict__ g3, const float* __restrict__ be3,
    const float* __restrict__ m3, const float* __restrict__ v3)
{
    __shared__ __align__(16) float w2s[HID * LP];
    __shared__ float s2s[HID], c2s[HID], w3s[HID];

    const int u   = blockIdx.x;
    const int tid = threadIdx.x;

    for (int i = tid; i < HID * LP; i += BATCH)
        w2s[i] = w2[u * HID * LP + i];
    if (tid < HID) {
        const int idx = u * HID + tid;
        float s = g2[idx] * rsqrtf(v2[idx] + EPSV);
        s2s[tid] = s;
        c2s[tid] = (b2[idx] - m2[idx]) * s + be2[idx];
        w3s[tid] = w3[idx];
    }
    __syncthreads();

    u64 yv2[LP / 2];
#pragma unroll
    for (int fp = 0; fp < LP / 2; fp++) {
        const float a  = g_y[u * (LP * BATCH) + (2 * fp) * BATCH + tid];
        const float bb = g_y[u * (LP * BATCH) + (2 * fp + 1) * BATCH + tid];
        yv2[fp] = pack2(a, bb);
    }

    float zacc = 0.0f;
#pragma unroll 1
    for (int o = 0; o < HID; o++) {
        const float4* wrow = reinterpret_cast<const float4*>(&w2s[o * LP]);
        u64 a0 = 0ULL, a1 = 0ULL;
#pragma unroll
        for (int j = 0; j < LP / 4; j++) {
            float4 v = wrow[j];
            u64 w01 = pack2(v.x, v.y);
            u64 w23 = pack2(v.z, v.w);
            fma2(a0, yv2[2 * j], w01);
            fma2(a1, yv2[2 * j + 1], w23);
        }
        float l0, h0, l1, h1;
        unpack2(l0, h0, a0);
        unpack2(l1, h1, a1);
        const float dsum = (l0 + h0) + (l1 + h1);
        const float hv = fmaxf(fmaf(dsum, s2s[o], c2s[o]), 0.0f);
        zacc = fmaf(hv, w3s[o], zacc);
    }

    const float s3 = g3[u] * rsqrtf(v3[u] + EPSV);
    const float z  = fmaf(zacc + b3[u] - m3[u], s3, be3[u]);
    g_z[u * BATCH + tid] = fmaxf(z, 0.0f);
}

// ---------------------------------------------------------------------------
// Kernel C: out[b][c] = sum_u z[u][b] * wf[c][u] + bf[c]
// ---------------------------------------------------------------------------
__global__ __launch_bounds__(BATCH) void final_linear_kernel(
    const float* __restrict__ wf, const float* __restrict__ bf,
    float* __restrict__ out)
{
    __shared__ float wfs[NU];
    const int c   = blockIdx.x;
    const int tid = threadIdx.x;

    for (int i = tid; i < NU; i += BATCH)
        wfs[i] = wf[c * NU + i];
    __syncthreads();

    float acc = bf[c];
#pragma unroll 4
    for (int u = 0; u < NU; u++)
        acc = fmaf(g_z[u * BATCH + tid], wfs[u], acc);

    out[tid * NCLS + c] = acc;
}

// ---------------------------------------------------------------------------
extern "C" void kernel_launch(void* const* d_in, const int* in_sizes, int n_in,
                              void* d_out, int out_size)
{
    const float* x   = (const float*)d_in[0];
    const float* w1  = (const float*)d_in[1];
    const float* b1  = (const float*)d_in[2];
    const float* g1  = (const float*)d_in[3];
    const float* be1 = (const float*)d_in[4];
    const float* m1  = (const float*)d_in[5];
    const float* v1  = (const float*)d_in[6];
    const float* w2  = (const float*)d_in[7];
    const float* b2  = (const float*)d_in[8];
    const float* g2  = (const float*)d_in[9];
    const float* be2 = (const float*)d_in[10];
    const float* m2  = (const float*)d_in[11];
    const float* v2  = (const float*)d_in[12];
    const float* w3  = (const float*)d_in[13];
    const float* b3  = (const float*)d_in[14];
    const float* g3  = (const float*)d_in[15];
    const float* be3 = (const float*)d_in[16];
    const float* m3  = (const float*)d_in[17];
    const float* v3  = (const float*)d_in[18];
    const float* wf  = (const float*)d_in[19];
    const float* bf  = (const float*)d_in[20];
    float* out = (float*)d_out;

    cudaFuncSetAttribute(conv_mma_kernel,
                         cudaFuncAttributeMaxDynamicSharedMemorySize, SMTOT);

    conv_mma_kernel<<<BATCH / BPC, CTHREADS, SMTOT>>>(x, w1, b1, g1, be1, m1, v1);
    unit_mlp_kernel<<<NU, BATCH>>>(w2, b2, g2, be2, m2, v2,
                                   w3, b3, g3, be3, m3, v3);
    final_linear_kernel<<<NCLS, BATCH>>>(wf, bf, out);
}

// round 9
// speedup vs baseline: 1.3880x; 1.0235x over previous
#include <cuda_runtime.h>
#include <cuda_fp16.h>
#include <stdint.h>
#include <math.h>

#define BATCH 256
#define LIN   608
#define FLT   19
#define POOL  7
#define LP    84
#define HID   100
#define NU    300
#define NCLS  50
#define EPSV  1e-5f

#define MTILES 19            // 304 unit rows
#define KSTEPS 5             // 5 x k16 = 80 >= 76
#define WARPS  14
#define CTHREADS (WARPS * 32)  // 448
#define NCH    28            // pools per chunk (2 per warp)
#define NCHUNKS 3            // 3 * 28 = 84

typedef unsigned long long u64;

// scratch (device globals)
__device__ float g_y[NU * LP * BATCH];   // [u][f][b]
__device__ float g_z[NU * BATCH];        // [u][b]

// ---------------------------------------------------------------------------
// smem byte offsets (dynamic smem) -- single B buffer: 91.7KB -> 2 CTAs/SM
// ---------------------------------------------------------------------------
#define ASZ    (MTILES * KSTEPS * 512)        // 48640 (fp16 single)
#define BBUF   (NCH * KSTEPS * 256)           // 35840
#define SA     0
#define SB0    (SA + ASZ)                     // 48640
#define SXH    (SB0 + BBUF)                   // 84480 (2432 fp16)
#define SBN_S  (SXH + 4864)                   // 89344
#define SBN_C  (SBN_S + 1200)                 // 90544
#define SMTOT  (SBN_C + 1200)                 // 91744

__device__ __forceinline__ uint32_t smem_u32(const void* p) {
    uint32_t a;
    asm("{ .reg .u64 t; cvta.to.shared.u64 t, %1; cvt.u32.u64 %0, t; }"
        : "=r"(a) : "l"(p));
    return a;
}

#define LDSM4(r, a) \
    asm volatile("ldmatrix.sync.aligned.m8n8.x4.shared.b16 {%0,%1,%2,%3}, [%4];" \
        : "=r"((r)[0]), "=r"((r)[1]), "=r"((r)[2]), "=r"((r)[3]) : "r"(a))
#define LDSM2(r, a) \
    asm volatile("ldmatrix.sync.aligned.m8n8.x2.shared.b16 {%0,%1}, [%2];" \
        : "=r"((r)[0]), "=r"((r)[1]) : "r"(a))

__device__ __forceinline__ void mma16816(float* c, const uint32_t* a, const uint32_t* b) {
    asm volatile(
        "mma.sync.aligned.m16n8k16.row.col.f32.f16.f16.f32 "
        "{%0,%1,%2,%3}, {%4,%5,%6,%7}, {%8,%9}, {%0,%1,%2,%3};"
        : "+f"(c[0]), "+f"(c[1]), "+f"(c[2]), "+f"(c[3])
        : "r"(a[0]), "r"(a[1]), "r"(a[2]), "r"(a[3]), "r"(b[0]), "r"(b[1]));
}

// epilogue for one m-tile, 2 pools: packed butterfly max + single store path
#define EPI2(ACCP, MT) do {                                                    \
    _Pragma("unroll") for (int r = 0; r < 2; r++) {                            \
        float mA = fmaxf((ACCP)[r][0], (ACCP)[r][1]);                          \
        float mB = fmaxf((ACCP)[r][2], (ACCP)[r][3]);                          \
        mA = fmaxf(mA, __shfl_xor_sync(0xFFFFFFFFu, mA, 1));                   \
        mB = fmaxf(mB, __shfl_xor_sync(0xFFFFFFFFu, mB, 1));                   \
        float cb = (lane & 1) ? mB : mA;                                       \
        cb = fmaxf(cb, __shfl_xor_sync(0xFFFFFFFFu, cb, 2));                   \
        if ((lane & 2) == 0) {                                                 \
            const int u = (MT) * 16 + (lane >> 2) + ((lane & 1) << 3);         \
            if (u < NU)                                                        \
                g_y[((size_t)u * LP + (fpool0 + r)) * BATCH + b] =             \
                    __expf(fmaf(cb, s1s[u], c1s[u]));                          \
        }                                                                      \
    }                                                                          \
} while (0)

// ---------------------------------------------------------------------------
// Kernel A: conv as warp-HMMA GEMM (fp16 single-pass) + fused BN/exp/maxpool
// grid 256 (1 batch/CTA), 14 warps, 2 CTAs/SM, single B buffer.
// ---------------------------------------------------------------------------
__global__ __launch_bounds__(CTHREADS, 2) void conv_mma_kernel(
    const float* __restrict__ x,  const float* __restrict__ w1,
    const float* __restrict__ b1, const float* __restrict__ g1,
    const float* __restrict__ be1,const float* __restrict__ m1,
    const float* __restrict__ v1)
{
    extern __shared__ __align__(128) char smem[];
    const uint32_t sb = smem_u32(smem);

    const int tid  = threadIdx.x;
    const int wid  = tid >> 5;
    const int lane = tid & 31;
    const int b    = blockIdx.x;

    __half* xh = reinterpret_cast<__half*>(smem + SXH);
    float* s1s = reinterpret_cast<float*>(smem + SBN_S);
    float* c1s = reinterpret_cast<float*>(smem + SBN_C);

    // --- BN constants ---
    for (int i = tid; i < NU; i += CTHREADS) {
        const float s = g1[i] * rsqrtf(v1[i] + EPSV);
        s1s[i] = s;
        c1s[i] = (b1[i] - m1[i]) * s + be1[i];
    }
    // --- x load + fp16 round ---
    {
        const float* xg = x + (size_t)b * (4 * LIN);
        for (int i = tid; i < 4 * LIN; i += CTHREADS)
            xh[i] = __float2half_rn(xg[i]);
    }
    // --- A build: W (304x80, zero-padded), ldmatrix-mat layout, fp16 ---
    {
        __half* aS = reinterpret_cast<__half*>(smem + SA);
        for (int i = tid; i < 304 * 80; i += CTHREADS) {
            const int ul = i / 80;
            const int k  = i % 80;
            float v = 0.f;
            if (ul < NU && k < 76) v = w1[ul * 76 + k];
            const int mt  = ul >> 4, s = k >> 4;
            const int mat = ((ul & 15) >> 3) | (((k & 15) >> 3) << 1);
            const int off = ((((mt * KSTEPS + s) << 2) + mat) << 6)
                            + ((ul & 7) << 3) + (k & 7);   // fp16 units
            aS[off] = __float2half_rn(v);
        }
    }
    __syncthreads();   // xh visible for B build

    const uint32_t aBase  = sb + SA + lane * 16;
    const uint32_t a4off  = ((lane >> 3) << 7) + ((lane & 7) << 4);
    const uint32_t a2off  = (((lane & 15) >> 3) << 7) + ((lane & 7) << 4);

    // build B chunk: pool-major im2col, fp16, half2-paired stores
#define BUILD_B(NT) do {                                                       \
        for (int i = tid; i < NCH * 8 * 40; i += CTHREADS) {                   \
            const int p  = i / 320;                                            \
            const int r  = i % 320;                                            \
            const int j  = r / 40;                                             \
            const int k  = (r % 40) * 2;                                       \
            const int jj = (j == 7) ? 0 : j;                                   \
            __half v0 = __float2half_rn(0.f), v1h = v0;                        \
            if (k < 76) {                                                      \
                const int base7 = 7 * ((NT) * NCH + p) + jj;                   \
                const int c0 = k / FLT, k1 = k + 1, c1 = k1 / FLT;             \
                v0  = xh[c0 * LIN + base7 + (k - c0 * FLT)];                   \
                v1h = xh[c1 * LIN + base7 + (k1 - c1 * FLT)];                  \
            }                                                                  \
            const int off = (((p * KSTEPS + (k >> 4)) << 1) + ((k & 15) >> 3)) * 128 \
                            + (j << 4) + ((k & 7) << 1);                       \
            *reinterpret_cast<__half2*>(smem + SB0 + off) =                    \
                __halves2half2(v0, v1h);                                       \
        }                                                                      \
    } while (0)

    BUILD_B(0);

    for (int nt = 0; nt < NCHUNKS; nt++) {
        __syncthreads();   // B[nt] built & visible

        const uint32_t bbase = sb + SB0 + (uint32_t)(2 * wid) * (KSTEPS * 256);

        // --- B fragments -> registers: 2 pools x 5 ksteps ---
        uint32_t bfr[2][KSTEPS][2];
#pragma unroll
        for (int p = 0; p < 2; p++) {
            const uint32_t pb = bbase + p * (KSTEPS * 256);
            LDSM4(&bfr[p][0][0], pb + a4off);            // s0,s1
            LDSM4(&bfr[p][2][0], pb + 512 + a4off);      // s2,s3
            LDSM2(&bfr[p][4][0], pb + 1024 + a2off);     // s4
        }

        __syncthreads();   // all warps took their fragments; buffer reusable

        // --- build next chunk while MMAs run ---
        if (nt + 1 < NCHUNKS)
            BUILD_B(nt + 1);

        const int fpool0 = nt * NCH + 2 * wid;

        // --- m-tile stream, acc ping-pong (deferred epilogue) ---
        float acc[2][2][4];
        uint32_t ah[KSTEPS][4];

#pragma unroll 1
        for (int mt = 0; mt < MTILES; mt++) {
            const int cur = mt & 1;
#pragma unroll
            for (int s = 0; s < KSTEPS; s++)
                LDSM4(ah[s], aBase + (mt * KSTEPS + s) * 512);
#pragma unroll
            for (int p = 0; p < 2; p++)
#pragma unroll
                for (int q = 0; q < 4; q++) acc[cur][p][q] = 0.f;

            if (mt > 0)
                EPI2(acc[cur ^ 1], mt - 1);

#pragma unroll
            for (int s = 0; s < KSTEPS; s++) {
                mma16816(acc[cur][0], ah[s], bfr[0][s]);
                mma16816(acc[cur][1], ah[s], bfr[1][s]);
            }
        }
        EPI2(acc[(MTILES - 1) & 1], MTILES - 1);
    }
}

// ---------------------------------------------------------------------------
// packed f32x2 helpers (MLP kernel)
// ---------------------------------------------------------------------------
__device__ __forceinline__ u64 pack2(float a, float b) {
    u64 r;
    asm("mov.b64 %0, {%1, %2};" : "=l"(r) : "f"(a), "f"(b));
    return r;
}
__device__ __forceinline__ void fma2(u64 &d, u64 a, u64 b) {
    asm("fma.rn.f32x2 %0, %1, %2, %0;" : "+l"(d) : "l"(a), "l"(b));
}
__device__ __forceinline__ void unpack2(float &lo, float &hi, u64 v) {
    unsigned a, b;
    asm("mov.b64 {%0, %1}, %2;" : "=r"(a), "=r"(b) : "l"(v));
    lo = __uint_as_float(a); hi = __uint_as_float(b);
}

// ---------------------------------------------------------------------------
// Kernel B: per-unit MLP 84->100 (BN+ReLU) -> 100->1 (BN+ReLU)  ->  z[u][b]
// ---------------------------------------------------------------------------
__global__ __launch_bounds__(BATCH) void unit_mlp_kernel(
    const float* __restrict__ w2, const float* __restrict__ b2,
    const float* __restrict__ g2, const float* __restrict__ be2,
    const float* __restrict__ m2, const float* __restrict__ v2,
    const float* __restrict__ w3, const float* __restrict__ b3,
    const float* __restrict__ g3, const float* __restrict__ be3,
    const float* __restrict__ m3, const float* __restrict__ v3)
{
    __shared__ __align__(16) float w2s[HID * LP];
    __shared__ float s2s[HID], c2s[HID], w3s[HID];

    const int u   = blockIdx.x;
    const int tid = threadIdx.x;

    for (int i = tid; i < HID * LP; i += BATCH)
        w2s[i] = w2[u * HID * LP + i];
    if (tid < HID) {
        const int idx = u * HID + tid;
        float s = g2[idx] * rsqrtf(v2[idx] + EPSV);
        s2s[tid] = s;
        c2s[tid] = (b2[idx] - m2[idx]) * s + be2[idx];
        w3s[tid] = w3[idx];
    }
    __syncthreads();

    u64 yv2[LP / 2];
#pragma unroll
    for (int fp = 0; fp < LP / 2; fp++) {
        const float a  = g_y[u * (LP * BATCH) + (2 * fp) * BATCH + tid];
        const float bb = g_y[u * (LP * BATCH) + (2 * fp + 1) * BATCH + tid];
        yv2[fp] = pack2(a, bb);
    }

    float zacc = 0.0f;
#pragma unroll 1
    for (int o = 0; o < HID; o++) {
        const float4* wrow = reinterpret_cast<const float4*>(&w2s[o * LP]);
        u64 a0 = 0ULL, a1 = 0ULL;
#pragma unroll
        for (int j = 0; j < LP / 4; j++) {
            float4 v = wrow[j];
            u64 w01 = pack2(v.x, v.y);
            u64 w23 = pack2(v.z, v.w);
            fma2(a0, yv2[2 * j], w01);
            fma2(a1, yv2[2 * j + 1], w23);
        }
        float l0, h0, l1, h1;
        unpack2(l0, h0, a0);
        unpack2(l1, h1, a1);
        const float dsum = (l0 + h0) + (l1 + h1);
        const float hv = fmaxf(fmaf(dsum, s2s[o], c2s[o]), 0.0f);
        zacc = fmaf(hv, w3s[o], zacc);
    }

    const float s3 = g3[u] * rsqrtf(v3[u] + EPSV);
    const float z  = fmaf(zacc + b3[u] - m3[u], s3, be3[u]);
    g_z[u * BATCH + tid] = fmaxf(z, 0.0f);
}

// ---------------------------------------------------------------------------
// Kernel C: out[b][c] = sum_u z[u][b] * wf[c][u] + bf[c]
// ---------------------------------------------------------------------------
__global__ __launch_bounds__(BATCH) void final_linear_kernel(
    const float* __restrict__ wf, const float* __restrict__ bf,
    float* __restrict__ out)
{
    __shared__ float wfs[NU];
    const int c   = blockIdx.x;
    const int tid = threadIdx.x;

    for (int i = tid; i < NU; i += BATCH)
        wfs[i] = wf[c * NU + i];
    __syncthreads();

    float acc = bf[c];
#pragma unroll 4
    for (int u = 0; u < NU; u++)
        acc = fmaf(g_z[u * BATCH + tid], wfs[u], acc);

    out[tid * NCLS + c] = acc;
}

// ---------------------------------------------------------------------------
extern "C" void kernel_launch(void* const* d_in, const int* in_sizes, int n_in,
                              void* d_out, int out_size)
{
    const float* x   = (const float*)d_in[0];
    const float* w1  = (const float*)d_in[1];
    const float* b1  = (const float*)d_in[2];
    const float* g1  = (const float*)d_in[3];
    const float* be1 = (const float*)d_in[4];
    const float* m1  = (const float*)d_in[5];
    const float* v1  = (const float*)d_in[6];
    const float* w2  = (const float*)d_in[7];
    const float* b2  = (const float*)d_in[8];
    const float* g2  = (const float*)d_in[9];
    const float* be2 = (const float*)d_in[10];
    const float* m2  = (const float*)d_in[11];
    const float* v2  = (const float*)d_in[12];
    const float* w3  = (const float*)d_in[13];
    const float* b3  = (const float*)d_in[14];
    const float* g3  = (const float*)d_in[15];
    const float* be3 = (const float*)d_in[16];
    const float* m3  = (const float*)d_in[17];
    const float* v3  = (const float*)d_in[18];
    const float* wf  = (const float*)d_in[19];
    const float* bf  = (const float*)d_in[20];
    float* out = (float*)d_out;

    cudaFuncSetAttribute(conv_mma_kernel,
                         cudaFuncAttributeMaxDynamicSharedMemorySize, SMTOT);

    conv_mma_kernel<<<BATCH, CTHREADS, SMTOT>>>(x, w1, b1, g1, be1, m1, v1);
    unit_mlp_kernel<<<NU, BATCH>>>(w2, b2, g2, be2, m2, v2,
                                   w3, b3, g3, be3, m3, v3);
    final_linear_kernel<<<NCLS, BATCH>>>(wf, bf, out);
}

// round 10
// speedup vs baseline: 1.9438x; 1.4004x over previous
#include <cuda_runtime.h>
#include <cuda_fp16.h>
#include <stdint.h>
#include <math.h>

#define BATCH 256
#define LIN   608
#define FLT   19
#define POOL  7
#define LP    84
#define HID   100
#define NU    300
#define NCLS  50
#define EPSV  1e-5f

#define MTILES 19              // 304 unit rows
#define KSTEPS 5               // K=80: 4 channels x 20 (kk=19 zero-padded in A)
#define WARPS  14
#define CTH    448
#define PPW    3               // pools per warp per round
#define ROUNDS 2               // 14*3*2 = 84 pools

typedef unsigned long long u64;

// scratch / precomputed (device globals)
__device__ float  g_y[NU * LP * BATCH];     // [u][f][b]
__device__ float  g_z[NU * BATCH];          // [u][b]
__device__ __half g_A[MTILES * KSTEPS * 256];  // 24320 halfs, ldmatrix layout
__device__ float  g_s1[NU], g_c1[NU];

// ---------------------------------------------------------------------------
// smem layout (dynamic): A 48640 | xt_even 4992 | xt_odd 4992 | s1 1200 | c1 1200
// ---------------------------------------------------------------------------
#define SA     0
#define ASZ    (MTILES * KSTEPS * 512)   // 48640
#define SXT    ASZ                       // two parity copies, 4992 B each
#define XTSZ   4992                      // 4 ch * 312 half2
#define SBN_S  (SXT + 2 * XTSZ)          // 58624
#define SBN_C  (SBN_S + 1200)
#define SMTOT  (SBN_C + 1200)            // 61024

__device__ __forceinline__ uint32_t smem_u32(const void* p) {
    uint32_t a;
    asm("{ .reg .u64 t; cvta.to.shared.u64 t, %1; cvt.u32.u64 %0, t; }"
        : "=r"(a) : "l"(p));
    return a;
}

#define LDSM4(r, a) \
    asm volatile("ldmatrix.sync.aligned.m8n8.x4.shared.b16 {%0,%1,%2,%3}, [%4];" \
        : "=r"((r)[0]), "=r"((r)[1]), "=r"((r)[2]), "=r"((r)[3]) : "r"(a))

__device__ __forceinline__ void mma16816(float* c, const uint32_t* a, const uint32_t* b) {
    asm volatile(
        "mma.sync.aligned.m16n8k16.row.col.f32.f16.f16.f32 "
        "{%0,%1,%2,%3}, {%4,%5,%6,%7}, {%8,%9}, {%0,%1,%2,%3};"
        : "+f"(c[0]), "+f"(c[1]), "+f"(c[2]), "+f"(c[3])
        : "r"(a[0]), "r"(a[1]), "r"(a[2]), "r"(a[3]), "r"(b[0]), "r"(b[1]));
}

// ---------------------------------------------------------------------------
// prep: build A (ldmatrix layout, K padded to 20/channel) + BN constants. Once.
// ---------------------------------------------------------------------------
__global__ void prep_kernel(
    const float* __restrict__ w1, const float* __restrict__ b1,
    const float* __restrict__ g1, const float* __restrict__ be1,
    const float* __restrict__ m1, const float* __restrict__ v1)
{
    const int idx = blockIdx.x * blockDim.x + threadIdx.x;
    if (idx < NU) {
        const float s = g1[idx] * rsqrtf(v1[idx] + EPSV);
        g_s1[idx] = s;
        g_c1[idx] = (b1[idx] - m1[idx]) * s + be1[idx];
    }
    for (int i = idx; i < 304 * 80; i += gridDim.x * blockDim.x) {
        const int ul = i / 80;
        const int k  = i % 80;
        const int c  = k / 20;
        const int kk = k - 20 * c;
        float v = 0.f;
        if (ul < NU && kk < FLT) v = w1[ul * 76 + c * FLT + kk];
        const int mt  = ul >> 4, s = k >> 4;
        const int mat = ((ul & 15) >> 3) | (((k & 15) >> 3) << 1);
        const int off = ((((mt * KSTEPS + s) << 2) + mat) << 6)
                        + ((ul & 7) << 3) + (k & 7);
        g_A[off] = __float2half_rn(v);
    }
}

// epilogue: one pool's m16n8 accumulators -> pooled max -> BN+exp -> g_y
#define EPI1(ACC, MT, F) do {                                                  \
    float mA = fmaxf((ACC)[0], (ACC)[1]);                                      \
    float mB = fmaxf((ACC)[2], (ACC)[3]);                                      \
    mA = fmaxf(mA, __shfl_xor_sync(0xFFFFFFFFu, mA, 1));                       \
    mB = fmaxf(mB, __shfl_xor_sync(0xFFFFFFFFu, mB, 1));                       \
    float cb = (lane & 1) ? mB : mA;                                           \
    cb = fmaxf(cb, __shfl_xor_sync(0xFFFFFFFFu, cb, 2));                       \
    if ((lane & 2) == 0) {                                                     \
        const int u = (MT) * 16 + (lane >> 2) + ((lane & 1) << 3);             \
        if (u < NU)                                                            \
            g_y[((size_t)u * LP + (F)) * BATCH + b] =                          \
                __expf(fmaf(cb, s1s[u], c1s[u]));                              \
    }                                                                          \
} while (0)

// ---------------------------------------------------------------------------
// Kernel A: conv as warp-HMMA GEMM, B fragments via direct LDS.32 from
// parity-shifted x copies (no im2col), A copied from precomputed global.
// grid 256 (1 batch/CTA), block 448, 2 CTAs/SM.
// ---------------------------------------------------------------------------
__global__ __launch_bounds__(CTH, 2) void conv_mma_kernel(const float* __restrict__ x)
{
    extern __shared__ __align__(128) char smem[];
    const uint32_t sb = smem_u32(smem);

    const int tid  = threadIdx.x;
    const int wid  = tid >> 5;
    const int lane = tid & 31;
    const int b    = blockIdx.x;

    float* s1s = reinterpret_cast<float*>(smem + SBN_S);
    float* c1s = reinterpret_cast<float*>(smem + SBN_C);

    // --- copy precomputed A (7 uint4 iters/thread) ---
    {
        const uint4* src = reinterpret_cast<const uint4*>(g_A);
        uint4* dst = reinterpret_cast<uint4*>(smem + SA);
        for (int i = tid; i < ASZ / 16; i += CTH) dst[i] = src[i];
    }
    // --- copy BN constants ---
    if (tid < NU) { s1s[tid] = g_s1[tid]; c1s[tid] = g_c1[tid]; }

    // --- build xt_even / xt_odd: half2 parity copies of x[b], padded to 624 ---
    {
        const float* xg = x + (size_t)b * (4 * LIN);
        __half2* xe = reinterpret_cast<__half2*>(smem + SXT);
        __half2* xo = reinterpret_cast<__half2*>(smem + SXT + XTSZ);
#pragma unroll
        for (int c = 0; c < 4; c++) {
            for (int t = tid; t < 312; t += CTH) {
                const int p0 = 2 * t;
                const float f0 = (p0     < LIN) ? xg[c * LIN + p0]     : 0.f;
                const float f1 = (p0 + 1 < LIN) ? xg[c * LIN + p0 + 1] : 0.f;
                const float f2 = (p0 + 2 < LIN) ? xg[c * LIN + p0 + 2] : 0.f;
                xe[c * 312 + t] = __halves2half2(__float2half_rn(f0), __float2half_rn(f1));
                xo[c * 312 + t] = __halves2half2(__float2half_rn(f1), __float2half_rn(f2));
            }
        }
    }
    __syncthreads();

    const uint32_t aBase = sb + SA + lane * 16;
    const int q    = lane & 3;
    const int slot = lane >> 2;
    const int jj   = (slot == 7) ? 0 : slot;

#pragma unroll
    for (int rnd = 0; rnd < ROUNDS; rnd++) {
        const int p0 = rnd * (WARPS * PPW) + wid * PPW;

        // --- B fragments: one LDS.32 per register, straight from xt copies ---
        uint32_t bfr[PPW][KSTEPS][2];
#pragma unroll
        for (int pp = 0; pp < PPW; pp++) {
            const int np = 7 * (p0 + pp) + jj;
#pragma unroll
            for (int s = 0; s < KSTEPS; s++) {
#pragma unroll
                for (int h = 0; h < 2; h++) {
                    const int k  = 16 * s + 8 * h + 2 * q;
                    const int c  = k / 20;
                    const int kk = k - 20 * c;
                    const int o  = np + kk;
                    const uint32_t addr = sb + SXT + (uint32_t)(o & 1) * XTSZ
                                        + (uint32_t)(c * 1248 + ((o >> 1) << 2));
                    asm volatile("ld.shared.b32 %0, [%1];"
                                 : "=r"(bfr[pp][s][h]) : "r"(addr));
                }
            }
        }

        // --- m-tile stream ---
#pragma unroll 1
        for (int mt = 0; mt < MTILES; mt++) {
            float acc[PPW][4];
#pragma unroll
            for (int pp = 0; pp < PPW; pp++)
#pragma unroll
                for (int z = 0; z < 4; z++) acc[pp][z] = 0.f;

            uint32_t a[4];
#pragma unroll
            for (int s = 0; s < KSTEPS; s++) {
                LDSM4(a, aBase + (mt * KSTEPS + s) * 512);
#pragma unroll
                for (int pp = 0; pp < PPW; pp++)
                    mma16816(acc[pp], a, bfr[pp][s]);
            }
#pragma unroll
            for (int pp = 0; pp < PPW; pp++)
                EPI1(acc[pp], mt, p0 + pp);
        }
    }
}

// ---------------------------------------------------------------------------
// packed f32x2 helpers (MLP kernel)
// ---------------------------------------------------------------------------
__device__ __forceinline__ u64 pack2(float a, float b) {
    u64 r;
    asm("mov.b64 %0, {%1, %2};" : "=l"(r) : "f"(a), "f"(b));
    return r;
}
__device__ __forceinline__ void fma2(u64 &d, u64 a, u64 b) {
    asm("fma.rn.f32x2 %0, %1, %2, %0;" : "+l"(d) : "l"(a), "l"(b));
}
__device__ __forceinline__ void unpack2(float &lo, float &hi, u64 v) {
    unsigned a, b;
    asm("mov.b64 {%0, %1}, %2;" : "=r"(a), "=r"(b) : "l"(v));
    lo = __uint_as_float(a); hi = __uint_as_float(b);
}

// ---------------------------------------------------------------------------
// Kernel B: per-unit MLP 84->100 (BN+ReLU) -> 100->1 (BN+ReLU)  ->  z[u][b]
// ---------------------------------------------------------------------------
__global__ __launch_bounds__(BATCH) void unit_mlp_kernel(
    const float* __restrict__ w2, const float* __restrict__ b2,
    const float* __restrict__ g2, const float* __restrict__ be2,
    const float* __restrict__ m2, const float* __restrict__ v2,
    const float* __restrict__ w3, const float* __restrict__ b3,
    const float* __restrict__ g3, const float* __restrict__ be3,
    const float* __restrict__ m3, const float* __restrict__ v3)
{
    __shared__ __align__(16) float w2s[HID * LP];
    __shared__ float s2s[HID], c2s[HID], w3s[HID];

    const int u   = blockIdx.x;
    const int tid = threadIdx.x;

    for (int i = tid; i < HID * LP; i += BATCH)
        w2s[i] = w2[u * HID * LP + i];
    if (tid < HID) {
        const int idx = u * HID + tid;
        float s = g2[idx] * rsqrtf(v2[idx] + EPSV);
        s2s[tid] = s;
        c2s[tid] = (b2[idx] - m2[idx]) * s + be2[idx];
        w3s[tid] = w3[idx];
    }
    __syncthreads();

    u64 yv2[LP / 2];
#pragma unroll
    for (int fp = 0; fp < LP / 2; fp++) {
        const float a  = g_y[u * (LP * BATCH) + (2 * fp) * BATCH + tid];
        const float bb = g_y[u * (LP * BATCH) + (2 * fp + 1) * BATCH + tid];
        yv2[fp] = pack2(a, bb);
    }

    float zacc = 0.0f;
#pragma unroll 1
    for (int o = 0; o < HID; o++) {
        const float4* wrow = reinterpret_cast<const float4*>(&w2s[o * LP]);
        u64 a0 = 0ULL, a1 = 0ULL;
#pragma unroll
        for (int j = 0; j < LP / 4; j++) {
            float4 v = wrow[j];
            u64 w01 = pack2(v.x, v.y);
            u64 w23 = pack2(v.z, v.w);
            fma2(a0, yv2[2 * j], w01);
            fma2(a1, yv2[2 * j + 1], w23);
        }
        float l0, h0, l1, h1;
        unpack2(l0, h0, a0);
        unpack2(l1, h1, a1);
        const float dsum = (l0 + h0) + (l1 + h1);
        const float hv = fmaxf(fmaf(dsum, s2s[o], c2s[o]), 0.0f);
        zacc = fmaf(hv, w3s[o], zacc);
    }

    const float s3 = g3[u] * rsqrtf(v3[u] + EPSV);
    const float z  = fmaf(zacc + b3[u] - m3[u], s3, be3[u]);
    g_z[u * BATCH + tid] = fmaxf(z, 0.0f);
}

// ---------------------------------------------------------------------------
// Kernel C: out[b][c] = sum_u z[u][b] * wf[c][u] + bf[c]
// ---------------------------------------------------------------------------
__global__ __launch_bounds__(BATCH) void final_linear_kernel(
    const float* __restrict__ wf, const float* __restrict__ bf,
    float* __restrict__ out)
{
    __shared__ float wfs[NU];
    const int c   = blockIdx.x;
    const int tid = threadIdx.x;

    for (int i = tid; i < NU; i += BATCH)
        wfs[i] = wf[c * NU + i];
    __syncthreads();

    float acc = bf[c];
#pragma unroll 4
    for (int u = 0; u < NU; u++)
        acc = fmaf(g_z[u * BATCH + tid], wfs[u], acc);

    out[tid * NCLS + c] = acc;
}

// ---------------------------------------------------------------------------
extern "C" void kernel_launch(void* const* d_in, const int* in_sizes, int n_in,
                              void* d_out, int out_size)
{
    const float* x   = (const float*)d_in[0];
    const float* w1  = (const float*)d_in[1];
    const float* b1  = (const float*)d_in[2];
    const float* g1  = (const float*)d_in[3];
    const float* be1 = (const float*)d_in[4];
    const float* m1  = (const float*)d_in[5];
    const float* v1  = (const float*)d_in[6];
    const float* w2  = (const float*)d_in[7];
    const float* b2  = (const float*)d_in[8];
    const float* g2  = (const float*)d_in[9];
    const float* be2 = (const float*)d_in[10];
    const float* m2  = (const float*)d_in[11];
    const float* v2  = (const float*)d_in[12];
    const float* w3  = (const float*)d_in[13];
    const float* b3  = (const float*)d_in[14];
    const float* g3  = (const float*)d_in[15];
    const float* be3 = (const float*)d_in[16];
    const float* m3  = (const float*)d_in[17];
    const float* v3  = (const float*)d_in[18];
    const float* wf  = (const float*)d_in[19];
    const float* bf  = (const float*)d_in[20];
    float* out = (float*)d_out;

    cudaFuncSetAttribute(conv_mma_kernel,
                         cudaFuncAttributeMaxDynamicSharedMemorySize, SMTOT);

    prep_kernel<<<64, 384>>>(w1, b1, g1, be1, m1, v1);
    conv_mma_kernel<<<BATCH, CTH, SMTOT>>>(x);
    unit_mlp_kernel<<<NU, BATCH>>>(w2, b2, g2, be2, m2, v2,
                                   w3, b3, g3, be3, m3, v3);
    final_linear_kernel<<<NCLS, BATCH>>>(wf, bf, out);
}

// round 11
// speedup vs baseline: 2.7949x; 1.4379x over previous
#include <cuda_runtime.h>
#include <cuda_fp16.h>
#include <cuda_bf16.h>
#include <stdint.h>
#include <math.h>

#define BATCH 256
#define LIN   608
#define FLT   19
#define POOL  7
#define LP    84
#define HID   100
#define NU    300
#define NCLS  50
#define EPSV  1e-5f

#define MTILES 19              // 304 unit rows
#define KSTEPS 5               // conv K=80: 4 ch x 20 (kk=19 zero-padded in A)
#define WARPS  14
#define CTH    448
#define PPW    2               // pools per warp per round (pairs -> packed y)
#define ROUNDS 3               // 14*2*3 = 84 pools

#define MKS    6               // MLP K = 96 (84 padded), 6 ksteps
#define MNT    13              // MLP N = 104 (100 padded), 13 ntiles

typedef unsigned long long u64;

// scratch / precomputed (device globals; zero-initialized at load -> pads stay 0)
__device__ float  g_z[NU * BATCH];                    // [u][b]
__device__ __half g_A[MTILES * KSTEPS * 256];         // conv A, ldmatrix layout
__device__ float  g_s1[NU], g_c1[NU];
__device__ uint2  g_yA[(size_t)NU * BATCH * 48];      // y frags: [u][b][fp] {hi,lo} bf16x2
__device__ uint2  g_w2f[(size_t)NU * MNT * MKS * 2 * 32]; // w2 frags {hi,lo}
__device__ float  g_part[6 * NCLS * BATCH];           // final split partials

// ---------------------------------------------------------------------------
// conv smem layout (dynamic): A 48640 | xt_even 4992 | xt_odd 4992 | s1 | c1
// ---------------------------------------------------------------------------
#define SA     0
#define ASZ    (MTILES * KSTEPS * 512)   // 48640
#define SXT    ASZ
#define XTSZ   4992                      // 4 ch * 312 half2
#define SBN_S  (SXT + 2 * XTSZ)          // 58624
#define SBN_C  (SBN_S + 1200)
#define SMTOT  (SBN_C + 1200)            // 61024

__device__ __forceinline__ uint32_t smem_u32(const void* p) {
    uint32_t a;
    asm("{ .reg .u64 t; cvta.to.shared.u64 t, %1; cvt.u32.u64 %0, t; }"
        : "=r"(a) : "l"(p));
    return a;
}

#define LDSM4(r, a) \
    asm volatile("ldmatrix.sync.aligned.m8n8.x4.shared.b16 {%0,%1,%2,%3}, [%4];" \
        : "=r"((r)[0]), "=r"((r)[1]), "=r"((r)[2]), "=r"((r)[3]) : "r"(a))

__device__ __forceinline__ void mma_f16(float* c, const uint32_t* a, const uint32_t* b) {
    asm volatile(
        "mma.sync.aligned.m16n8k16.row.col.f32.f16.f16.f32 "
        "{%0,%1,%2,%3}, {%4,%5,%6,%7}, {%8,%9}, {%0,%1,%2,%3};"
        : "+f"(c[0]), "+f"(c[1]), "+f"(c[2]), "+f"(c[3])
        : "r"(a[0]), "r"(a[1]), "r"(a[2]), "r"(a[3]), "r"(b[0]), "r"(b[1]));
}
__device__ __forceinline__ void mma_bf16(float* c, const uint32_t* a, const uint32_t* b) {
    asm volatile(
        "mma.sync.aligned.m16n8k16.row.col.f32.bf16.bf16.f32 "
        "{%0,%1,%2,%3}, {%4,%5,%6,%7}, {%8,%9}, {%0,%1,%2,%3};"
        : "+f"(c[0]), "+f"(c[1]), "+f"(c[2]), "+f"(c[3])
        : "r"(a[0]), "r"(a[1]), "r"(a[2]), "r"(a[3]), "r"(b[0]), "r"(b[1]));
}

__device__ __forceinline__ uint32_t pack_bf2(float a, float b) {
    __nv_bfloat162 t = __floats2bfloat162_rn(a, b);
    return *reinterpret_cast<uint32_t*>(&t);
}

// ---------------------------------------------------------------------------
// prep: conv A frags + BN1 consts + w2 fragment-direct layout. Once per launch.
// ---------------------------------------------------------------------------
__global__ void prep_kernel(
    const float* __restrict__ w1, const float* __restrict__ w2,
    const float* __restrict__ b1, const float* __restrict__ g1,
    const float* __restrict__ be1,const float* __restrict__ m1,
    const float* __restrict__ v1)
{
    const int idx = blockIdx.x * blockDim.x + threadIdx.x;
    const int stride = gridDim.x * blockDim.x;
    if (idx < NU) {
        const float s = g1[idx] * rsqrtf(v1[idx] + EPSV);
        g_s1[idx] = s;
        g_c1[idx] = (b1[idx] - m1[idx]) * s + be1[idx];
    }
    // conv A (ldmatrix layout, K padded to 20/channel)
    for (int i = idx; i < 304 * 80; i += stride) {
        const int ul = i / 80;
        const int k  = i % 80;
        const int c  = k / 20;
        const int kk = k - 20 * c;
        float v = 0.f;
        if (ul < NU && kk < FLT) v = w1[ul * 76 + c * FLT + kk];
        const int mt  = ul >> 4, s = k >> 4;
        const int mat = ((ul & 15) >> 3) | (((k & 15) >> 3) << 1);
        const int off = ((((mt * KSTEPS + s) << 2) + mat) << 6)
                        + ((ul & 7) << 3) + (k & 7);
        g_A[off] = __float2half_rn(v);
    }
    // w2 fragment-direct layout: [u][nt][ks][reg][lane] -> uint2{hi_pair, lo_pair}
    for (int i = idx; i < NU * (MNT * MKS * 2 * 32); i += stride) {
        const int lane = i & 31;
        const int rg   = (i >> 5) & 1;
        const int ks   = (i >> 6) % MKS;
        const int nt   = (i / (MKS * 64)) % MNT;
        const int u    = i / (MNT * MKS * 64);
        const int o    = nt * 8 + (lane >> 2);
        const int k0   = 16 * ks + 2 * (lane & 3) + 8 * rg;
        float v0 = 0.f, v1 = 0.f;
        if (o < HID) {
            if (k0     < LP) v0 = w2[((size_t)u * HID + o) * LP + k0];
            if (k0 + 1 < LP) v1 = w2[((size_t)u * HID + o) * LP + k0 + 1];
        }
        const float h0 = __bfloat162float(__float2bfloat16(v0));
        const float h1 = __bfloat162float(__float2bfloat16(v1));
        uint2 r;
        r.x = pack_bf2(v0, v1);
        r.y = pack_bf2(v0 - h0, v1 - h1);
        g_w2f[i] = r;
    }
}

// conv epilogue: 2 pools -> pooled max -> BN+exp -> packed bf16 hi/lo y frag
#define EPI_PAIR(ACC, MT, FP) do {                                             \
    float cb[2];                                                               \
    _Pragma("unroll") for (int pp = 0; pp < 2; pp++) {                         \
        float mA = fmaxf((ACC)[pp][0], (ACC)[pp][1]);                          \
        float mB = fmaxf((ACC)[pp][2], (ACC)[pp][3]);                          \
        mA = fmaxf(mA, __shfl_xor_sync(0xFFFFFFFFu, mA, 1));                   \
        mB = fmaxf(mB, __shfl_xor_sync(0xFFFFFFFFu, mB, 1));                   \
        float c0 = (lane & 1) ? mB : mA;                                       \
        cb[pp] = fmaxf(c0, __shfl_xor_sync(0xFFFFFFFFu, c0, 2));               \
    }                                                                          \
    if ((lane & 2) == 0) {                                                     \
        const int u = (MT) * 16 + (lane >> 2) + ((lane & 1) << 3);             \
        if (u < NU) {                                                          \
            const float y0 = __expf(fmaf(cb[0], s1s[u], c1s[u]));              \
            const float y1 = __expf(fmaf(cb[1], s1s[u], c1s[u]));              \
            const float h0 = __bfloat162float(__float2bfloat16(y0));           \
            const float h1 = __bfloat162float(__float2bfloat16(y1));           \
            uint2 v;                                                           \
            v.x = pack_bf2(y0, y1);                                            \
            v.y = pack_bf2(y0 - h0, y1 - h1);                                  \
            g_yA[((size_t)u * BATCH + b) * 48 + (FP)] = v;                     \
        }                                                                      \
    }                                                                          \
} while (0)

// ---------------------------------------------------------------------------
// Kernel A: conv as warp-HMMA GEMM (fp16), direct-LDS B frags, y written as
// packed bf16 hi/lo A-fragments for the MLP GEMM.
// ---------------------------------------------------------------------------
__global__ __launch_bounds__(CTH, 2) void conv_mma_kernel(const float* __restrict__ x)
{
    extern __shared__ __align__(128) char smem[];
    const uint32_t sb = smem_u32(smem);

    const int tid  = threadIdx.x;
    const int wid  = tid >> 5;
    const int lane = tid & 31;
    const int b    = blockIdx.x;

    float* s1s = reinterpret_cast<float*>(smem + SBN_S);
    float* c1s = reinterpret_cast<float*>(smem + SBN_C);

    {
        const uint4* src = reinterpret_cast<const uint4*>(g_A);
        uint4* dst = reinterpret_cast<uint4*>(smem + SA);
        for (int i = tid; i < ASZ / 16; i += CTH) dst[i] = src[i];
    }
    if (tid < NU) { s1s[tid] = g_s1[tid]; c1s[tid] = g_c1[tid]; }

    {
        const float* xg = x + (size_t)b * (4 * LIN);
        __half2* xe = reinterpret_cast<__half2*>(smem + SXT);
        __half2* xo = reinterpret_cast<__half2*>(smem + SXT + XTSZ);
#pragma unroll
        for (int c = 0; c < 4; c++) {
            for (int t = tid; t < 312; t += CTH) {
                const int p0 = 2 * t;
                const float f0 = (p0     < LIN) ? xg[c * LIN + p0]     : 0.f;
                const float f1 = (p0 + 1 < LIN) ? xg[c * LIN + p0 + 1] : 0.f;
                const float f2 = (p0 + 2 < LIN) ? xg[c * LIN + p0 + 2] : 0.f;
                xe[c * 312 + t] = __halves2half2(__float2half_rn(f0), __float2half_rn(f1));
                xo[c * 312 + t] = __halves2half2(__float2half_rn(f1), __float2half_rn(f2));
            }
        }
    }
    __syncthreads();

    const uint32_t aBase = sb + SA + lane * 16;
    const int q    = lane & 3;
    const int slot = lane >> 2;
    const int jj   = (slot == 7) ? 0 : slot;

#pragma unroll
    for (int rnd = 0; rnd < ROUNDS; rnd++) {
        const int p0 = rnd * (WARPS * PPW) + wid * PPW;
        const int FP = rnd * WARPS + wid;   // f-pair index = p0/2

        uint32_t bfr[PPW][KSTEPS][2];
#pragma unroll
        for (int pp = 0; pp < PPW; pp++) {
            const int np = 7 * (p0 + pp) + jj;
#pragma unroll
            for (int s = 0; s < KSTEPS; s++) {
#pragma unroll
                for (int h = 0; h < 2; h++) {
                    const int k  = 16 * s + 8 * h + 2 * q;
                    const int c  = k / 20;
                    const int kk = k - 20 * c;
                    const int o  = np + kk;
                    const uint32_t addr = sb + SXT + (uint32_t)(o & 1) * XTSZ
                                        + (uint32_t)(c * 1248 + ((o >> 1) << 2));
                    asm volatile("ld.shared.b32 %0, [%1];"
                                 : "=r"(bfr[pp][s][h]) : "r"(addr));
                }
            }
        }

#pragma unroll 1
        for (int mt = 0; mt < MTILES; mt++) {
            float acc[PPW][4];
#pragma unroll
            for (int pp = 0; pp < PPW; pp++)
#pragma unroll
                for (int z = 0; z < 4; z++) acc[pp][z] = 0.f;

            uint32_t a[4];
#pragma unroll
            for (int s = 0; s < KSTEPS; s++) {
                LDSM4(a, aBase + (mt * KSTEPS + s) * 512);
                mma_f16(acc[0], a, bfr[0][s]);
                mma_f16(acc[1], a, bfr[1][s]);
            }
            EPI_PAIR(acc, mt, FP);
        }
    }
}

// ---------------------------------------------------------------------------
// Kernel B: per-unit MLP GEMM via bf16 3-pass HMMA, fragment-direct LDGs.
// grid 300 (u), block 256 (8 warps; warp w owns batch-tiles w and w+8).
// ---------------------------------------------------------------------------
__global__ __launch_bounds__(256, 2) void unit_mlp_mma(
    const float* __restrict__ b2, const float* __restrict__ g2,
    const float* __restrict__ be2,const float* __restrict__ m2,
    const float* __restrict__ v2, const float* __restrict__ w3,
    const float* __restrict__ b3, const float* __restrict__ g3,
    const float* __restrict__ be3,const float* __restrict__ m3,
    const float* __restrict__ v3)
{
    __shared__ float s2s[HID], c2s[HID], w3s[HID];

    const int u    = blockIdx.x;
    const int tid  = threadIdx.x;
    const int wid  = tid >> 5;
    const int lane = tid & 31;
    const int g    = lane >> 2;
    const int q    = lane & 3;

    if (tid < HID) {
        const int idx = u * HID + tid;
        const float s = g2[idx] * rsqrtf(v2[idx] + EPSV);
        s2s[tid] = s;
        c2s[tid] = (b2[idx] - m2[idx]) * s + be2[idx];
        w3s[tid] = w3[idx];
    }
    __syncthreads();

#pragma unroll 1
    for (int half = 0; half < 2; half++) {
        const int bt = wid + 8 * half;

        // A fragments (y) for this batch-tile: 24 LDG.64
        uint32_t ah[MKS][4], al[MKS][4];
        const uint2* yA = g_yA + ((size_t)u * BATCH + bt * 16) * 48;
#pragma unroll
        for (int ks = 0; ks < MKS; ks++) {
            uint2 t0 = yA[(size_t)(g    ) * 48 + 8 * ks + q    ];
            uint2 t1 = yA[(size_t)(g + 8) * 48 + 8 * ks + q    ];
            uint2 t2 = yA[(size_t)(g    ) * 48 + 8 * ks + q + 4];
            uint2 t3 = yA[(size_t)(g + 8) * 48 + 8 * ks + q + 4];
            ah[ks][0] = t0.x; al[ks][0] = t0.y;
            ah[ks][1] = t1.x; al[ks][1] = t1.y;
            ah[ks][2] = t2.x; al[ks][2] = t2.y;
            ah[ks][3] = t3.x; al[ks][3] = t3.y;
        }

        float zp0 = 0.f, zp1 = 0.f;
#pragma unroll 1
        for (int nt = 0; nt < MNT; nt++) {
            uint32_t bh[MKS][2], bl[MKS][2];
            const uint2* wf2 = g_w2f + (((size_t)u * MNT + nt) * MKS * 2) * 32 + lane;
#pragma unroll
            for (int ks = 0; ks < MKS; ks++) {
                uint2 r0 = wf2[(ks * 2    ) * 32];
                uint2 r1 = wf2[(ks * 2 + 1) * 32];
                bh[ks][0] = r0.x; bl[ks][0] = r0.y;
                bh[ks][1] = r1.x; bl[ks][1] = r1.y;
            }
            float acc[4] = {0.f, 0.f, 0.f, 0.f};
#pragma unroll
            for (int ks = 0; ks < MKS; ks++) {
                mma_bf16(acc, ah[ks], bh[ks]);
                mma_bf16(acc, ah[ks], bl[ks]);
                mma_bf16(acc, al[ks], bh[ks]);
            }
            const int o0 = nt * 8 + 2 * q;
            const int o1 = o0 + 1;
            if (o0 < HID) {
                const float s = s2s[o0], c = c2s[o0], w = w3s[o0];
                zp0 = fmaf(fmaxf(fmaf(acc[0], s, c), 0.f), w, zp0);
                zp1 = fmaf(fmaxf(fmaf(acc[2], s, c), 0.f), w, zp1);
            }
            if (o1 < HID) {
                const float s = s2s[o1], c = c2s[o1], w = w3s[o1];
                zp0 = fmaf(fmaxf(fmaf(acc[1], s, c), 0.f), w, zp0);
                zp1 = fmaf(fmaxf(fmaf(acc[3], s, c), 0.f), w, zp1);
            }
        }
        zp0 += __shfl_xor_sync(0xFFFFFFFFu, zp0, 1);
        zp0 += __shfl_xor_sync(0xFFFFFFFFu, zp0, 2);
        zp1 += __shfl_xor_sync(0xFFFFFFFFu, zp1, 1);
        zp1 += __shfl_xor_sync(0xFFFFFFFFu, zp1, 2);
        if (q == 0) {
            const float s3 = g3[u] * rsqrtf(v3[u] + EPSV);
            const float c3 = (b3[u] - m3[u]) * s3 + be3[u];
            g_z[u * BATCH + bt * 16 + g    ] = fmaxf(fmaf(zp0, s3, c3), 0.f);
            g_z[u * BATCH + bt * 16 + g + 8] = fmaxf(fmaf(zp1, s3, c3), 0.f);
        }
    }
}

// ---------------------------------------------------------------------------
// Kernel C1: split-K final linear partials. grid (NCLS, 6), block 256.
// ---------------------------------------------------------------------------
__global__ __launch_bounds__(BATCH) void final_split_kernel(const float* __restrict__ wf)
{
    __shared__ float wfs[50];
    const int c   = blockIdx.x;
    const int sp  = blockIdx.y;
    const int tid = threadIdx.x;

    if (tid < 50) wfs[tid] = wf[c * NU + sp * 50 + tid];
    __syncthreads();

    const float* zp = g_z + (size_t)sp * 50 * BATCH + tid;
    float a0 = 0.f, a1 = 0.f;
#pragma unroll
    for (int j = 0; j < 25; j++) {
        a0 = fmaf(zp[(2 * j    ) * BATCH], wfs[2 * j    ], a0);
        a1 = fmaf(zp[(2 * j + 1) * BATCH], wfs[2 * j + 1], a1);
    }
    g_part[(sp * NCLS + c) * BATCH + tid] = a0 + a1;
}

// ---------------------------------------------------------------------------
// Kernel C2: reduce partials + bias. grid NCLS, block 256.
// ---------------------------------------------------------------------------
__global__ __launch_bounds__(BATCH) void final_reduce_kernel(
    const float* __restrict__ bf, float* __restrict__ out)
{
    const int c   = blockIdx.x;
    const int tid = threadIdx.x;
    float s = bf[c];
#pragma unroll
    for (int sp = 0; sp < 6; sp++)
        s += g_part[(sp * NCLS + c) * BATCH + tid];
    out[tid * NCLS + c] = s;
}

// ---------------------------------------------------------------------------
extern "C" void kernel_launch(void* const* d_in, const int* in_sizes, int n_in,
                              void* d_out, int out_size)
{
    const float* x   = (const float*)d_in[0];
    const float* w1  = (const float*)d_in[1];
    const float* b1  = (const float*)d_in[2];
    const float* g1  = (const float*)d_in[3];
    const float* be1 = (const float*)d_in[4];
    const float* m1  = (const float*)d_in[5];
    const float* v1  = (const float*)d_in[6];
    const float* w2  = (const float*)d_in[7];
    const float* b2  = (const float*)d_in[8];
    const float* g2  = (const float*)d_in[9];
    const float* be2 = (const float*)d_in[10];
    const float* m2  = (const float*)d_in[11];
    const float* v2  = (const float*)d_in[12];
    const float* w3  = (const float*)d_in[13];
    const float* b3  = (const float*)d_in[14];
    const float* g3  = (const float*)d_in[15];
    const float* be3 = (const float*)d_in[16];
    const float* m3  = (const float*)d_in[17];
    const float* v3  = (const float*)d_in[18];
    const float* wf  = (const float*)d_in[19];
    const float* bf  = (const float*)d_in[20];
    float* out = (float*)d_out;

    cudaFuncSetAttribute(conv_mma_kernel,
                         cudaFuncAttributeMaxDynamicSharedMemorySize, SMTOT);

    prep_kernel<<<128, 384>>>(w1, w2, b1, g1, be1, m1, v1);
    conv_mma_kernel<<<BATCH, CTH, SMTOT>>>(x);
    unit_mlp_mma<<<NU, 256>>>(b2, g2, be2, m2, v2, w3, b3, g3, be3, m3, v3);
    final_split_kernel<<<dim3(NCLS, 6), BATCH>>>(wf);
    final_reduce_kernel<<<NCLS, BATCH>>>(bf, out);
}

// round 12
// speedup vs baseline: 2.9462x; 1.0542x over previous
#include <cuda_runtime.h>
#include <cuda_fp16.h>
#include <cuda_bf16.h>
#include <stdint.h>
#include <math.h>

#define BATCH 256
#define LIN   608
#define FLT   19
#define POOL  7
#define LP    84
#define HID   100
#define NU    300
#define NCLS  50
#define EPSV  1e-5f

#define MTILES 19              // 304 unit rows
#define KSTEPS 5               // conv K=80: 4 ch x 20 (kk=19 zero-padded in A)
#define WARPS  14
#define CTH    448
#define PPW    2               // pools per warp per round (pairs -> packed y)
#define ROUNDS 3               // 14*2*3 = 84 pools

#define MKS    6               // MLP K = 96 (84 padded), 6 ksteps
#define MNT    13              // MLP N = 104 (100 padded), 13 ntiles
#define W2FSL  (MNT * MKS * 2 * 32)   // uint2 per unit slice = 4992

typedef unsigned long long u64;

// scratch / precomputed (device globals; zero-initialized -> pads stay 0)
__device__ float  g_z[NU * BATCH];                    // [u][b]
__device__ __half g_A[MTILES * KSTEPS * 256];         // conv A, ldmatrix layout
__device__ float  g_s1[NU], g_c1[NU];
__device__ uint2  g_yA[(size_t)NU * BATCH * 48];      // y frags: [u][b][fp] {hi,lo}
__device__ uint2  g_w2f[(size_t)NU * W2FSL];          // w2 frags {hi,lo}
__device__ float  g_part[6 * NCLS * BATCH];           // final split partials

// ---------------------------------------------------------------------------
// conv smem layout (dynamic): A 48640 | xt_even 4992 | xt_odd 4992 | s1 | c1
// ---------------------------------------------------------------------------
#define SA     0
#define ASZ    (MTILES * KSTEPS * 512)   // 48640
#define SXT    ASZ
#define XTSZ   4992                      // 4 ch * 312 half2
#define SBN_S  (SXT + 2 * XTSZ)          // 58624
#define SBN_C  (SBN_S + 1200)
#define SMTOT  (SBN_C + 1200)            // 61024

__device__ __forceinline__ uint32_t smem_u32(const void* p) {
    uint32_t a;
    asm("{ .reg .u64 t; cvta.to.shared.u64 t, %1; cvt.u32.u64 %0, t; }"
        : "=r"(a) : "l"(p));
    return a;
}

#define LDSM4(r, a) \
    asm volatile("ldmatrix.sync.aligned.m8n8.x4.shared.b16 {%0,%1,%2,%3}, [%4];" \
        : "=r"((r)[0]), "=r"((r)[1]), "=r"((r)[2]), "=r"((r)[3]) : "r"(a))

__device__ __forceinline__ void mma_f16(float* c, const uint32_t* a, const uint32_t* b) {
    asm volatile(
        "mma.sync.aligned.m16n8k16.row.col.f32.f16.f16.f32 "
        "{%0,%1,%2,%3}, {%4,%5,%6,%7}, {%8,%9}, {%0,%1,%2,%3};"
        : "+f"(c[0]), "+f"(c[1]), "+f"(c[2]), "+f"(c[3])
        : "r"(a[0]), "r"(a[1]), "r"(a[2]), "r"(a[3]), "r"(b[0]), "r"(b[1]));
}
__device__ __forceinline__ void mma_bf16(float* c, const uint32_t* a, const uint32_t* b) {
    asm volatile(
        "mma.sync.aligned.m16n8k16.row.col.f32.bf16.bf16.f32 "
        "{%0,%1,%2,%3}, {%4,%5,%6,%7}, {%8,%9}, {%0,%1,%2,%3};"
        : "+f"(c[0]), "+f"(c[1]), "+f"(c[2]), "+f"(c[3])
        : "r"(a[0]), "r"(a[1]), "r"(a[2]), "r"(a[3]), "r"(b[0]), "r"(b[1]));
}

__device__ __forceinline__ uint32_t pack_bf2(float a, float b) {
    __nv_bfloat162 t = __floats2bfloat162_rn(a, b);
    return *reinterpret_cast<uint32_t*>(&t);
}

// ---------------------------------------------------------------------------
// prep: conv A frags + BN1 consts + w2 fragment-direct layout. Once per launch.
// ---------------------------------------------------------------------------
__global__ void prep_kernel(
    const float* __restrict__ w1, const float* __restrict__ w2,
    const float* __restrict__ b1, const float* __restrict__ g1,
    const float* __restrict__ be1,const float* __restrict__ m1,
    const float* __restrict__ v1)
{
    const int idx = blockIdx.x * blockDim.x + threadIdx.x;
    const int stride = gridDim.x * blockDim.x;
    if (idx < NU) {
        const float s = g1[idx] * rsqrtf(v1[idx] + EPSV);
        g_s1[idx] = s;
        g_c1[idx] = (b1[idx] - m1[idx]) * s + be1[idx];
    }
    // conv A (ldmatrix layout, K padded to 20/channel)
    for (int i = idx; i < 304 * 80; i += stride) {
        const int ul = i / 80;
        const int k  = i % 80;
        const int c  = k / 20;
        const int kk = k - 20 * c;
        float v = 0.f;
        if (ul < NU && kk < FLT) v = w1[ul * 76 + c * FLT + kk];
        const int mt  = ul >> 4, s = k >> 4;
        const int mat = ((ul & 15) >> 3) | (((k & 15) >> 3) << 1);
        const int off = ((((mt * KSTEPS + s) << 2) + mat) << 6)
                        + ((ul & 7) << 3) + (k & 7);
        g_A[off] = __float2half_rn(v);
    }
    // w2 fragment-direct layout: [u][nt][ks][reg][lane] -> uint2{hi_pair, lo_pair}
    for (int i = idx; i < NU * W2FSL; i += stride) {
        const int lane = i & 31;
        const int rg   = (i >> 5) & 1;
        const int ks   = (i >> 6) % MKS;
        const int nt   = (i / (MKS * 64)) % MNT;
        const int u    = i / W2FSL;
        const int o    = nt * 8 + (lane >> 2);
        const int k0   = 16 * ks + 2 * (lane & 3) + 8 * rg;
        float v0 = 0.f, v1 = 0.f;
        if (o < HID) {
            if (k0     < LP) v0 = w2[((size_t)u * HID + o) * LP + k0];
            if (k0 + 1 < LP) v1 = w2[((size_t)u * HID + o) * LP + k0 + 1];
        }
        const float h0 = __bfloat162float(__float2bfloat16(v0));
        const float h1 = __bfloat162float(__float2bfloat16(v1));
        uint2 r;
        r.x = pack_bf2(v0, v1);
        r.y = pack_bf2(v0 - h0, v1 - h1);
        g_w2f[i] = r;
    }
}

// conv epilogue: 2 pools -> pooled max -> BN+exp -> packed bf16 hi/lo y frag
#define EPI_PAIR(ACC, MT, FP) do {                                             \
    float cb[2];                                                               \
    _Pragma("unroll") for (int pp = 0; pp < 2; pp++) {                         \
        float mA = fmaxf((ACC)[pp][0], (ACC)[pp][1]);                          \
        float mB = fmaxf((ACC)[pp][2], (ACC)[pp][3]);                          \
        mA = fmaxf(mA, __shfl_xor_sync(0xFFFFFFFFu, mA, 1));                   \
        mB = fmaxf(mB, __shfl_xor_sync(0xFFFFFFFFu, mB, 1));                   \
        float c0 = (lane & 1) ? mB : mA;                                       \
        cb[pp] = fmaxf(c0, __shfl_xor_sync(0xFFFFFFFFu, c0, 2));               \
    }                                                                          \
    if ((lane & 2) == 0) {                                                     \
        const int u = (MT) * 16 + (lane >> 2) + ((lane & 1) << 3);             \
        if (u < NU) {                                                          \
            const float y0 = __expf(fmaf(cb[0], s1s[u], c1s[u]));              \
            const float y1 = __expf(fmaf(cb[1], s1s[u], c1s[u]));              \
            const float h0 = __bfloat162float(__float2bfloat16(y0));           \
            const float h1 = __bfloat162float(__float2bfloat16(y1));           \
            uint2 v;                                                           \
            v.x = pack_bf2(y0, y1);                                            \
            v.y = pack_bf2(y0 - h0, y1 - h1);                                  \
            g_yA[((size_t)u * BATCH + b) * 48 + (FP)] = v;                     \
        }                                                                      \
    }                                                                          \
} while (0)

// ---------------------------------------------------------------------------
// Kernel A: conv as warp-HMMA GEMM (fp16), direct-LDS B frags, y written as
// packed bf16 hi/lo A-fragments for the MLP GEMM.
// ---------------------------------------------------------------------------
__global__ __launch_bounds__(CTH, 2) void conv_mma_kernel(const float* __restrict__ x)
{
    extern __shared__ __align__(128) char smem[];
    const uint32_t sb = smem_u32(smem);

    const int tid  = threadIdx.x;
    const int wid  = tid >> 5;
    const int lane = tid & 31;
    const int b    = blockIdx.x;

    float* s1s = reinterpret_cast<float*>(smem + SBN_S);
    float* c1s = reinterpret_cast<float*>(smem + SBN_C);

    {
        const uint4* src = reinterpret_cast<const uint4*>(g_A);
        uint4* dst = reinterpret_cast<uint4*>(smem + SA);
        for (int i = tid; i < ASZ / 16; i += CTH) dst[i] = src[i];
    }
    if (tid < NU) { s1s[tid] = g_s1[tid]; c1s[tid] = g_c1[tid]; }

    {
        const float* xg = x + (size_t)b * (4 * LIN);
        __half2* xe = reinterpret_cast<__half2*>(smem + SXT);
        __half2* xo = reinterpret_cast<__half2*>(smem + SXT + XTSZ);
#pragma unroll
        for (int c = 0; c < 4; c++) {
            for (int t = tid; t < 312; t += CTH) {
                const int p0 = 2 * t;
                const float f0 = (p0     < LIN) ? xg[c * LIN + p0]     : 0.f;
                const float f1 = (p0 + 1 < LIN) ? xg[c * LIN + p0 + 1] : 0.f;
                const float f2 = (p0 + 2 < LIN) ? xg[c * LIN + p0 + 2] : 0.f;
                xe[c * 312 + t] = __halves2half2(__float2half_rn(f0), __float2half_rn(f1));
                xo[c * 312 + t] = __halves2half2(__float2half_rn(f1), __float2half_rn(f2));
            }
        }
    }
    __syncthreads();

    const uint32_t aBase = sb + SA + lane * 16;
    const int q    = lane & 3;
    const int slot = lane >> 2;
    const int jj   = (slot == 7) ? 0 : slot;

#pragma unroll
    for (int rnd = 0; rnd < ROUNDS; rnd++) {
        const int p0 = rnd * (WARPS * PPW) + wid * PPW;
        const int FP = rnd * WARPS + wid;   // f-pair index = p0/2

        uint32_t bfr[PPW][KSTEPS][2];
#pragma unroll
        for (int pp = 0; pp < PPW; pp++) {
            const int np = 7 * (p0 + pp) + jj;
#pragma unroll
            for (int s = 0; s < KSTEPS; s++) {
#pragma unroll
                for (int h = 0; h < 2; h++) {
                    const int k  = 16 * s + 8 * h + 2 * q;
                    const int c  = k / 20;
                    const int kk = k - 20 * c;
                    const int o  = np + kk;
                    const uint32_t addr = sb + SXT + (uint32_t)(o & 1) * XTSZ
                                        + (uint32_t)(c * 1248 + ((o >> 1) << 2));
                    asm volatile("ld.shared.b32 %0, [%1];"
                                 : "=r"(bfr[pp][s][h]) : "r"(addr));
                }
            }
        }

#pragma unroll 1
        for (int mt = 0; mt < MTILES; mt++) {
            float acc[PPW][4];
#pragma unroll
            for (int pp = 0; pp < PPW; pp++)
#pragma unroll
                for (int z = 0; z < 4; z++) acc[pp][z] = 0.f;

            uint32_t a[4];
#pragma unroll
            for (int s = 0; s < KSTEPS; s++) {
                LDSM4(a, aBase + (mt * KSTEPS + s) * 512);
                mma_f16(acc[0], a, bfr[0][s]);
                mma_f16(acc[1], a, bfr[1][s]);
            }
            EPI_PAIR(acc, mt, FP);
        }
    }
}

// ---------------------------------------------------------------------------
// Kernel B: per-unit MLP GEMM via bf16 3-pass HMMA.
// w2f slice staged in smem once per CTA (kills 16x redundant global reads).
// grid 300 (u), block 256 (8 warps; warp w owns batch-tiles w and w+8).
// ---------------------------------------------------------------------------
__global__ __launch_bounds__(256, 2) void unit_mlp_mma(
    const float* __restrict__ b2, const float* __restrict__ g2,
    const float* __restrict__ be2,const float* __restrict__ m2,
    const float* __restrict__ v2, const float* __restrict__ w3,
    const float* __restrict__ b3, const float* __restrict__ g3,
    const float* __restrict__ be3,const float* __restrict__ m3,
    const float* __restrict__ v3)
{
    __shared__ __align__(16) uint2 w2s[W2FSL];          // 39936 B
    __shared__ float s2s[HID], c2s[HID], w3s[HID];

    const int u    = blockIdx.x;
    const int tid  = threadIdx.x;
    const int wid  = tid >> 5;
    const int lane = tid & 31;
    const int g    = lane >> 2;
    const int q    = lane & 3;

    // stage w2f slice (coalesced uint4)
    {
        const uint4* src = reinterpret_cast<const uint4*>(g_w2f + (size_t)u * W2FSL);
        uint4* dst = reinterpret_cast<uint4*>(w2s);
        for (int i = tid; i < W2FSL / 2; i += 256) dst[i] = src[i];
    }
    if (tid < HID) {
        const int idx = u * HID + tid;
        const float s = g2[idx] * rsqrtf(v2[idx] + EPSV);
        s2s[tid] = s;
        c2s[tid] = (b2[idx] - m2[idx]) * s + be2[idx];
        w3s[tid] = w3[idx];
    }
    __syncthreads();

#pragma unroll 1
    for (int half = 0; half < 2; half++) {
        const int bt = wid + 8 * half;

        // A fragments (y) for this batch-tile: 24 LDG.64
        uint32_t ah[MKS][4], al[MKS][4];
        const uint2* yA = g_yA + ((size_t)u * BATCH + bt * 16) * 48;
#pragma unroll
        for (int ks = 0; ks < MKS; ks++) {
            uint2 t0 = yA[(size_t)(g    ) * 48 + 8 * ks + q    ];
            uint2 t1 = yA[(size_t)(g + 8) * 48 + 8 * ks + q    ];
            uint2 t2 = yA[(size_t)(g    ) * 48 + 8 * ks + q + 4];
            uint2 t3 = yA[(size_t)(g + 8) * 48 + 8 * ks + q + 4];
            ah[ks][0] = t0.x; al[ks][0] = t0.y;
            ah[ks][1] = t1.x; al[ks][1] = t1.y;
            ah[ks][2] = t2.x; al[ks][2] = t2.y;
            ah[ks][3] = t3.x; al[ks][3] = t3.y;
        }

        float zp0 = 0.f, zp1 = 0.f;
#pragma unroll 1
        for (int nt = 0; nt < MNT; nt++) {
            uint32_t bh[MKS][2], bl[MKS][2];
            const uint2* wf2 = w2s + (nt * MKS * 2) * 32 + lane;
#pragma unroll
            for (int ks = 0; ks < MKS; ks++) {
                uint2 r0 = wf2[(ks * 2    ) * 32];
                uint2 r1 = wf2[(ks * 2 + 1) * 32];
                bh[ks][0] = r0.x; bl[ks][0] = r0.y;
                bh[ks][1] = r1.x; bl[ks][1] = r1.y;
            }
            float acc[4] = {0.f, 0.f, 0.f, 0.f};
#pragma unroll
            for (int ks = 0; ks < MKS; ks++) {
                mma_bf16(acc, ah[ks], bh[ks]);
                mma_bf16(acc, ah[ks], bl[ks]);
                mma_bf16(acc, al[ks], bh[ks]);
            }
            const int o0 = nt * 8 + 2 * q;
            const int o1 = o0 + 1;
            if (o0 < HID) {
                const float s = s2s[o0], c = c2s[o0], w = w3s[o0];
                zp0 = fmaf(fmaxf(fmaf(acc[0], s, c), 0.f), w, zp0);
                zp1 = fmaf(fmaxf(fmaf(acc[2], s, c), 0.f), w, zp1);
            }
            if (o1 < HID) {
                const float s = s2s[o1], c = c2s[o1], w = w3s[o1];
                zp0 = fmaf(fmaxf(fmaf(acc[1], s, c), 0.f), w, zp0);
                zp1 = fmaf(fmaxf(fmaf(acc[3], s, c), 0.f), w, zp1);
            }
        }
        zp0 += __shfl_xor_sync(0xFFFFFFFFu, zp0, 1);
        zp0 += __shfl_xor_sync(0xFFFFFFFFu, zp0, 2);
        zp1 += __shfl_xor_sync(0xFFFFFFFFu, zp1, 1);
        zp1 += __shfl_xor_sync(0xFFFFFFFFu, zp1, 2);
        if (q == 0) {
            const float s3 = g3[u] * rsqrtf(v3[u] + EPSV);
            const float c3 = (b3[u] - m3[u]) * s3 + be3[u];
            g_z[u * BATCH + bt * 16 + g    ] = fmaxf(fmaf(zp0, s3, c3), 0.f);
            g_z[u * BATCH + bt * 16 + g + 8] = fmaxf(fmaf(zp1, s3, c3), 0.f);
        }
    }
}

// ---------------------------------------------------------------------------
// Kernel C1: split-K final linear partials. grid (NCLS, 6), block 256.
// ---------------------------------------------------------------------------
__global__ __launch_bounds__(BATCH) void final_split_kernel(const float* __restrict__ wf)
{
    __shared__ float wfs[50];
    const int c   = blockIdx.x;
    const int sp  = blockIdx.y;
    const int tid = threadIdx.x;

    if (tid < 50) wfs[tid] = wf[c * NU + sp * 50 + tid];
    __syncthreads();

    const float* zp = g_z + (size_t)sp * 50 * BATCH + tid;
    float a0 = 0.f, a1 = 0.f;
#pragma unroll
    for (int j = 0; j < 25; j++) {
        a0 = fmaf(zp[(2 * j    ) * BATCH], wfs[2 * j    ], a0);
        a1 = fmaf(zp[(2 * j + 1) * BATCH], wfs[2 * j + 1], a1);
    }
    g_part[(sp * NCLS + c) * BATCH + tid] = a0 + a1;
}

// ---------------------------------------------------------------------------
// Kernel C2: reduce partials + bias. grid NCLS, block 256.
// ---------------------------------------------------------------------------
__global__ __launch_bounds__(BATCH) void final_reduce_kernel(
    const float* __restrict__ bf, float* __restrict__ out)
{
    const int c   = blockIdx.x;
    const int tid = threadIdx.x;
    float s = bf[c];
#pragma unroll
    for (int sp = 0; sp < 6; sp++)
        s += g_part[(sp * NCLS + c) * BATCH + tid];
    out[tid * NCLS + c] = s;
}

// ---------------------------------------------------------------------------
extern "C" void kernel_launch(void* const* d_in, const int* in_sizes, int n_in,
                              void* d_out, int out_size)
{
    const float* x   = (const float*)d_in[0];
    const float* w1  = (const float*)d_in[1];
    const float* b1  = (const float*)d_in[2];
    const float* g1  = (const float*)d_in[3];
    const float* be1 = (const float*)d_in[4];
    const float* m1  = (const float*)d_in[5];
    const float* v1  = (const float*)d_in[6];
    const float* w2  = (const float*)d_in[7];
    const float* b2  = (const float*)d_in[8];
    const float* g2  = (const float*)d_in[9];
    const float* be2 = (const float*)d_in[10];
    const float* m2  = (const float*)d_in[11];
    const float* v2  = (const float*)d_in[12];
    const float* w3  = (const float*)d_in[13];
    const float* b3  = (const float*)d_in[14];
    const float* g3  = (const float*)d_in[15];
    const float* be3 = (const float*)d_in[16];
    const float* m3  = (const float*)d_in[17];
    const float* v3  = (const float*)d_in[18];
    const float* wf  = (const float*)d_in[19];
    const float* bf  = (const float*)d_in[20];
    float* out = (float*)d_out;

    cudaFuncSetAttribute(conv_mma_kernel,
                         cudaFuncAttributeMaxDynamicSharedMemorySize, SMTOT);

    prep_kernel<<<256, 512>>>(w1, w2, b1, g1, be1, m1, v1);
    conv_mma_kernel<<<BATCH, CTH, SMTOT>>>(x);
    unit_mlp_mma<<<NU, 256>>>(b2, g2, be2, m2, v2, w3, b3, g3, be3, m3, v3);
    final_split_kernel<<<dim3(NCLS, 6), BATCH>>>(wf);
    final_reduce_kernel<<<NCLS, BATCH>>>(bf, out);
}